// round 5
// baseline (speedup 1.0000x reference)
#include <cuda_runtime.h>
#include <math.h>
#include <stdint.h>

// ---------------- problem constants ----------------
#define NB   16
#define NT   512
#define TOK  (NB*NT)        // 8192 tokens
#define HD   768
#define T3   (3*HD)         // 2304
#define DFF  3072
#define NHH  12
#define DH   64
#define NLB  9
#define NBH  (NB*NHH)       // 192
#define NLAY 4

// ---------------- scratch (static device globals; no runtime alloc) ----------------
__device__ float g_x[TOK*HD];
__device__ float g_qkv[TOK*T3];
__device__ float g_scores[(size_t)NBH*NT*NT];   // 201 MB
__device__ float g_ctx[TOK*HD];
__device__ float g_y[TOK*HD];
__device__ float g_ff[TOK*DFF];
__device__ float g_logits[TOK*NLB];
__device__ float g_llh[NB];

// ---------------- tf32 helpers ----------------
__device__ __forceinline__ void split_tf32(float x, float& hi, float& lo) {
    uint32_t h;
    asm("cvt.rna.tf32.f32 %0, %1;" : "=r"(h) : "f"(x));
    float hf = __uint_as_float(h);
    float r = x - hf;
    uint32_t l;
    asm("cvt.rna.tf32.f32 %0, %1;" : "=r"(l) : "f"(r));
    hi = hf; lo = __uint_as_float(l);
}

__device__ __forceinline__ void split4(float4 v, float4& h, float4& l) {
    split_tf32(v.x, h.x, l.x);
    split_tf32(v.y, h.y, l.y);
    split_tf32(v.z, h.z, l.z);
    split_tf32(v.w, h.w, l.w);
}

__device__ __forceinline__ void mma_tf32(float* c, const uint32_t* a, const uint32_t* b) {
    asm volatile(
        "mma.sync.aligned.m16n8k8.row.col.f32.tf32.tf32.f32 "
        "{%0,%1,%2,%3}, {%4,%5,%6,%7}, {%8,%9}, {%0,%1,%2,%3};"
        : "+f"(c[0]), "+f"(c[1]), "+f"(c[2]), "+f"(c[3])
        : "r"(a[0]), "r"(a[1]), "r"(a[2]), "r"(a[3]), "r"(b[0]), "r"(b[1]));
}

__device__ __forceinline__ float gelu_tanh(float v) {
    float u = 0.7978845608028654f * (v + 0.044715f * v * v * v);
    return 0.5f * v * (1.f + tanhf(u));
}

// ---------------- reductions ----------------
__device__ __forceinline__ void reduce2_256(float& a, float& b) {
    __shared__ float sa[8], sb[8];
    #pragma unroll
    for (int o = 16; o; o >>= 1) {
        a += __shfl_xor_sync(0xffffffffu, a, o);
        b += __shfl_xor_sync(0xffffffffu, b, o);
    }
    int w = threadIdx.x >> 5;
    if ((threadIdx.x & 31) == 0) { sa[w] = a; sb[w] = b; }
    __syncthreads();
    a = 0.f; b = 0.f;
    #pragma unroll
    for (int i = 0; i < 8; i++) { a += sa[i]; b += sb[i]; }
}

// ---------------- embedding + LN ----------------
__global__ void __launch_bounds__(256) embed_ln_kernel(
    const int* __restrict__ ids, const int* __restrict__ tt,
    const float* __restrict__ we, const float* __restrict__ pe, const float* __restrict__ te,
    const float* __restrict__ sc, const float* __restrict__ bi, float* __restrict__ x)
{
    int tok = blockIdx.x;
    int t   = tok & (NT - 1);
    int tid = threadIdx.x;
    const float* w  = we + (size_t)ids[tok] * HD;
    const float* p  = pe + (size_t)t * HD;
    const float* ty = te + (size_t)tt[tok] * HD;
    float e[3]; float sum = 0.f, sq = 0.f;
    #pragma unroll
    for (int i = 0; i < 3; i++) {
        int c = tid + i * 256;
        float v = w[c] + p[c] + ty[c];
        e[i] = v; sum += v; sq += v * v;
    }
    reduce2_256(sum, sq);
    float mean = sum * (1.f / HD);
    float var  = sq * (1.f / HD) - mean * mean;
    float inv  = rsqrtf(var + 1e-12f);
    #pragma unroll
    for (int i = 0; i < 3; i++) {
        int c = tid + i * 256;
        x[(size_t)tok * HD + c] = (e[i] - mean) * inv * sc[c] + bi[c];
    }
}

// ---------------- residual + LN ----------------
__global__ void __launch_bounds__(256) ln_res_kernel(
    const float* __restrict__ xin, const float* __restrict__ y,
    const float* __restrict__ sc, const float* __restrict__ bi, float* __restrict__ xout)
{
    int tok = blockIdx.x;
    int tid = threadIdx.x;
    float e[3]; float sum = 0.f, sq = 0.f;
    #pragma unroll
    for (int i = 0; i < 3; i++) {
        int c = tid + i * 256;
        float v = xin[(size_t)tok * HD + c] + y[(size_t)tok * HD + c];
        e[i] = v; sum += v; sq += v * v;
    }
    reduce2_256(sum, sq);
    float mean = sum * (1.f / HD);
    float var  = sq * (1.f / HD) - mean * mean;
    float inv  = rsqrtf(var + 1e-12f);
    #pragma unroll
    for (int i = 0; i < 3; i++) {
        int c = tid + i * 256;
        xout[(size_t)tok * HD + c] = (e[i] - mean) * inv * sc[c] + bi[c];
    }
}

// ================= 3xTF32 GEMM (pre-split SMEM): C = A @ B (+bias / gelu) =================
// Tile 128x128x16, 256 threads (8 warps as 2x4), warp tile 64x32.
template<int EPI>
__global__ void __launch_bounds__(256) gemm_tf32(
    const float* __restrict__ A, const float* __restrict__ B,
    const float* __restrict__ bias, float* __restrict__ C,
    int M, int N, int K)
{
    __shared__ float AsH[16][136];
    __shared__ float AsL[16][136];
    __shared__ float BsH[16][136];
    __shared__ float BsL[16][136];

    const int tid  = threadIdx.x;
    const int m0   = blockIdx.y * 128;
    const int n0   = blockIdx.x * 128;
    const int lane = tid & 31, warp = tid >> 5;
    const int wm = (warp >> 2) * 64;
    const int wn = (warp & 3) * 32;
    const int g  = lane >> 2, tg = lane & 3;

    const int arow = tid >> 1, acol = (tid & 1) * 8;
    const int brow = tid >> 4, bcol = (tid & 15) * 8;
    const float* Ap = A + (size_t)(m0 + arow) * K + acol;
    const float* Bp = B + (size_t)brow * N + n0 + bcol;

    float4 ra0 = *(const float4*)(Ap);
    float4 ra1 = *(const float4*)(Ap + 4);
    float4 rb0 = *(const float4*)(Bp);
    float4 rb1 = *(const float4*)(Bp + 4);

    float acc[16][4];
    #pragma unroll
    for (int i = 0; i < 16; i++) { acc[i][0] = acc[i][1] = acc[i][2] = acc[i][3] = 0.f; }

    const int TT = K >> 4;
    for (int t = 0; t < TT; t++) {
        {
            float4 h0, l0, h1, l1;
            split4(ra0, h0, l0); split4(ra1, h1, l1);
            AsH[acol + 0][arow] = h0.x; AsL[acol + 0][arow] = l0.x;
            AsH[acol + 1][arow] = h0.y; AsL[acol + 1][arow] = l0.y;
            AsH[acol + 2][arow] = h0.z; AsL[acol + 2][arow] = l0.z;
            AsH[acol + 3][arow] = h0.w; AsL[acol + 3][arow] = l0.w;
            AsH[acol + 4][arow] = h1.x; AsL[acol + 4][arow] = l1.x;
            AsH[acol + 5][arow] = h1.y; AsL[acol + 5][arow] = l1.y;
            AsH[acol + 6][arow] = h1.z; AsL[acol + 6][arow] = l1.z;
            AsH[acol + 7][arow] = h1.w; AsL[acol + 7][arow] = l1.w;
            split4(rb0, h0, l0); split4(rb1, h1, l1);
            *(float4*)&BsH[brow][bcol]     = h0;
            *(float4*)&BsL[brow][bcol]     = l0;
            *(float4*)&BsH[brow][bcol + 4] = h1;
            *(float4*)&BsL[brow][bcol + 4] = l1;
        }
        __syncthreads();

        if (t + 1 < TT) {
            int ko = (t + 1) * 16;
            ra0 = *(const float4*)(Ap + ko);
            ra1 = *(const float4*)(Ap + ko + 4);
            rb0 = *(const float4*)(Bp + (size_t)ko * N);
            rb1 = *(const float4*)(Bp + (size_t)ko * N + 4);
        }

        #pragma unroll
        for (int kk = 0; kk < 16; kk += 8) {
            uint32_t ahi[16], alo[16], bhi[8], blo[8];
            #pragma unroll
            for (int mf = 0; mf < 4; mf++) {
                int mb = wm + mf * 16 + g;
                ahi[mf*4+0] = __float_as_uint(AsH[kk + tg][mb]);
                alo[mf*4+0] = __float_as_uint(AsL[kk + tg][mb]);
                ahi[mf*4+1] = __float_as_uint(AsH[kk + tg][mb + 8]);
                alo[mf*4+1] = __float_as_uint(AsL[kk + tg][mb + 8]);
                ahi[mf*4+2] = __float_as_uint(AsH[kk + tg + 4][mb]);
                alo[mf*4+2] = __float_as_uint(AsL[kk + tg + 4][mb]);
                ahi[mf*4+3] = __float_as_uint(AsH[kk + tg + 4][mb + 8]);
                alo[mf*4+3] = __float_as_uint(AsL[kk + tg + 4][mb + 8]);
            }
            #pragma unroll
            for (int nf = 0; nf < 4; nf++) {
                int nb = wn + nf * 8 + g;
                bhi[nf*2+0] = __float_as_uint(BsH[kk + tg][nb]);
                blo[nf*2+0] = __float_as_uint(BsL[kk + tg][nb]);
                bhi[nf*2+1] = __float_as_uint(BsH[kk + tg + 4][nb]);
                blo[nf*2+1] = __float_as_uint(BsL[kk + tg + 4][nb]);
            }
            #pragma unroll
            for (int mf = 0; mf < 4; mf++)
                #pragma unroll
                for (int nf = 0; nf < 4; nf++) {
                    float* c = acc[mf * 4 + nf];
                    mma_tf32(c, &alo[mf*4], &bhi[nf*2]);
                    mma_tf32(c, &ahi[mf*4], &blo[nf*2]);
                    mma_tf32(c, &ahi[mf*4], &bhi[nf*2]);
                }
        }
        __syncthreads();
    }

    #pragma unroll
    for (int mf = 0; mf < 4; mf++) {
        #pragma unroll
        for (int nf = 0; nf < 4; nf++) {
            const float* c = acc[mf * 4 + nf];
            int mrow = m0 + wm + mf * 16 + g;
            int ncol = n0 + wn + nf * 8 + tg * 2;
            float b0 = bias[ncol], b1 = bias[ncol + 1];
            float v0 = c[0] + b0, v1 = c[1] + b1, v2 = c[2] + b0, v3 = c[3] + b1;
            if (EPI == 1) { v0 = gelu_tanh(v0); v1 = gelu_tanh(v1); v2 = gelu_tanh(v2); v3 = gelu_tanh(v3); }
            C[(size_t)mrow * N + ncol]           = v0;
            C[(size_t)mrow * N + ncol + 1]       = v1;
            C[(size_t)(mrow + 8) * N + ncol]     = v2;
            C[(size_t)(mrow + 8) * N + ncol + 1] = v3;
        }
    }
}

// ================= 3xTF32 QK^T (pre-split SMEM) =================
__global__ void __launch_bounds__(256) qk_tf32(
    const float* __restrict__ qkv, float* __restrict__ scores)
{
    __shared__ float AsH[16][136];
    __shared__ float AsL[16][136];
    __shared__ float BsH[16][136];
    __shared__ float BsL[16][136];

    const int tid  = threadIdx.x;
    const int bh   = blockIdx.z;
    const int b    = bh / NHH, h = bh % NHH;
    const int m0   = blockIdx.y * 128;
    const int n0   = blockIdx.x * 128;
    const int lane = tid & 31, warp = tid >> 5;
    const int wm = (warp >> 2) * 64;
    const int wn = (warp & 3) * 32;
    const int g  = lane >> 2, tg = lane & 3;

    const int arow = tid >> 1, acol = (tid & 1) * 8;
    const int bnr  = tid >> 1, bkc  = (tid & 1) * 8;
    const float* Ap = qkv + (size_t)(b * NT + m0 + arow) * T3 + h * DH + acol;
    const float* Bp = qkv + (size_t)(b * NT + n0 + bnr) * T3 + HD + h * DH + bkc;

    float4 ra0 = *(const float4*)(Ap);
    float4 ra1 = *(const float4*)(Ap + 4);
    float4 rb0 = *(const float4*)(Bp);
    float4 rb1 = *(const float4*)(Bp + 4);

    float acc[16][4];
    #pragma unroll
    for (int i = 0; i < 16; i++) { acc[i][0] = acc[i][1] = acc[i][2] = acc[i][3] = 0.f; }

    const int TT = DH >> 4;   // 4
    for (int t = 0; t < TT; t++) {
        {
            float4 h0, l0, h1, l1;
            split4(ra0, h0, l0); split4(ra1, h1, l1);
            AsH[acol + 0][arow] = h0.x; AsL[acol + 0][arow] = l0.x;
            AsH[acol + 1][arow] = h0.y; AsL[acol + 1][arow] = l0.y;
            AsH[acol + 2][arow] = h0.z; AsL[acol + 2][arow] = l0.z;
            AsH[acol + 3][arow] = h0.w; AsL[acol + 3][arow] = l0.w;
            AsH[acol + 4][arow] = h1.x; AsL[acol + 4][arow] = l1.x;
            AsH[acol + 5][arow] = h1.y; AsL[acol + 5][arow] = l1.y;
            AsH[acol + 6][arow] = h1.z; AsL[acol + 6][arow] = l1.z;
            AsH[acol + 7][arow] = h1.w; AsL[acol + 7][arow] = l1.w;
            split4(rb0, h0, l0); split4(rb1, h1, l1);
            BsH[bkc + 0][bnr] = h0.x; BsL[bkc + 0][bnr] = l0.x;
            BsH[bkc + 1][bnr] = h0.y; BsL[bkc + 1][bnr] = l0.y;
            BsH[bkc + 2][bnr] = h0.z; BsL[bkc + 2][bnr] = l0.z;
            BsH[bkc + 3][bnr] = h0.w; BsL[bkc + 3][bnr] = l0.w;
            BsH[bkc + 4][bnr] = h1.x; BsL[bkc + 4][bnr] = l1.x;
            BsH[bkc + 5][bnr] = h1.y; BsL[bkc + 5][bnr] = l1.y;
            BsH[bkc + 6][bnr] = h1.z; BsL[bkc + 6][bnr] = l1.z;
            BsH[bkc + 7][bnr] = h1.w; BsL[bkc + 7][bnr] = l1.w;
        }
        __syncthreads();

        if (t + 1 < TT) {
            int ko = (t + 1) * 16;
            ra0 = *(const float4*)(Ap + ko);
            ra1 = *(const float4*)(Ap + ko + 4);
            rb0 = *(const float4*)(Bp + ko);
            rb1 = *(const float4*)(Bp + ko + 4);
        }

        #pragma unroll
        for (int kk = 0; kk < 16; kk += 8) {
            uint32_t ahi[16], alo[16], bhi[8], blo[8];
            #pragma unroll
            for (int mf = 0; mf < 4; mf++) {
                int mb = wm + mf * 16 + g;
                ahi[mf*4+0] = __float_as_uint(AsH[kk + tg][mb]);
                alo[mf*4+0] = __float_as_uint(AsL[kk + tg][mb]);
                ahi[mf*4+1] = __float_as_uint(AsH[kk + tg][mb + 8]);
                alo[mf*4+1] = __float_as_uint(AsL[kk + tg][mb + 8]);
                ahi[mf*4+2] = __float_as_uint(AsH[kk + tg + 4][mb]);
                alo[mf*4+2] = __float_as_uint(AsL[kk + tg + 4][mb]);
                ahi[mf*4+3] = __float_as_uint(AsH[kk + tg + 4][mb + 8]);
                alo[mf*4+3] = __float_as_uint(AsL[kk + tg + 4][mb + 8]);
            }
            #pragma unroll
            for (int nf = 0; nf < 4; nf++) {
                int nb = wn + nf * 8 + g;
                bhi[nf*2+0] = __float_as_uint(BsH[kk + tg][nb]);
                blo[nf*2+0] = __float_as_uint(BsL[kk + tg][nb]);
                bhi[nf*2+1] = __float_as_uint(BsH[kk + tg + 4][nb]);
                blo[nf*2+1] = __float_as_uint(BsL[kk + tg + 4][nb]);
            }
            #pragma unroll
            for (int mf = 0; mf < 4; mf++)
                #pragma unroll
                for (int nf = 0; nf < 4; nf++) {
                    float* c = acc[mf * 4 + nf];
                    mma_tf32(c, &alo[mf*4], &bhi[nf*2]);
                    mma_tf32(c, &ahi[mf*4], &blo[nf*2]);
                    mma_tf32(c, &ahi[mf*4], &bhi[nf*2]);
                }
        }
        __syncthreads();
    }

    float* out = scores + (size_t)bh * NT * NT;
    #pragma unroll
    for (int mf = 0; mf < 4; mf++)
        #pragma unroll
        for (int nf = 0; nf < 4; nf++) {
            const float* c = acc[mf * 4 + nf];
            int mrow = m0 + wm + mf * 16 + g;
            int ncol = n0 + wn + nf * 8 + tg * 2;
            out[(size_t)mrow * NT + ncol]           = c[0];
            out[(size_t)mrow * NT + ncol + 1]       = c[1];
            out[(size_t)(mrow + 8) * NT + ncol]     = c[2];
            out[(size_t)(mrow + 8) * NT + ncol + 1] = c[3];
        }
}

// ================= 3xTF32 S@V (pre-split SMEM) =================
// Tile 128x64x16, 8 warps as 2x4, warp tile 64x16 (mf=4, nf=2).
__global__ void __launch_bounds__(256) av_tf32(
    const float* __restrict__ scores, const float* __restrict__ qkv, float* __restrict__ ctx)
{
    __shared__ float AsH[16][136];
    __shared__ float AsL[16][136];
    __shared__ float BsH[16][72];
    __shared__ float BsL[16][72];

    const int tid  = threadIdx.x;
    const int bh   = blockIdx.y;
    const int b    = bh / NHH, h = bh % NHH;
    const int m0   = blockIdx.x * 128;
    const int lane = tid & 31, warp = tid >> 5;
    const int wm = (warp >> 2) * 64;
    const int wn = (warp & 3) * 16;
    const int g  = lane >> 2, tg = lane & 3;

    const int arow = tid >> 1, acol = (tid & 1) * 8;
    const int brow = tid >> 4, bcol = (tid & 15) * 4;
    const float* Ap = scores + (size_t)bh * NT * NT + (size_t)(m0 + arow) * NT + acol;
    const float* Bp = qkv + (size_t)(b * NT + brow) * T3 + 2 * HD + h * DH + bcol;

    float4 ra0 = *(const float4*)(Ap);
    float4 ra1 = *(const float4*)(Ap + 4);
    float4 rb0 = *(const float4*)(Bp);

    float acc[8][4];
    #pragma unroll
    for (int i = 0; i < 8; i++) { acc[i][0] = acc[i][1] = acc[i][2] = acc[i][3] = 0.f; }

    const int TT = NT >> 4;   // 32
    for (int t = 0; t < TT; t++) {
        {
            float4 h0, l0, h1, l1;
            split4(ra0, h0, l0); split4(ra1, h1, l1);
            AsH[acol + 0][arow] = h0.x; AsL[acol + 0][arow] = l0.x;
            AsH[acol + 1][arow] = h0.y; AsL[acol + 1][arow] = l0.y;
            AsH[acol + 2][arow] = h0.z; AsL[acol + 2][arow] = l0.z;
            AsH[acol + 3][arow] = h0.w; AsL[acol + 3][arow] = l0.w;
            AsH[acol + 4][arow] = h1.x; AsL[acol + 4][arow] = l1.x;
            AsH[acol + 5][arow] = h1.y; AsL[acol + 5][arow] = l1.y;
            AsH[acol + 6][arow] = h1.z; AsL[acol + 6][arow] = l1.z;
            AsH[acol + 7][arow] = h1.w; AsL[acol + 7][arow] = l1.w;
            split4(rb0, h0, l0);
            *(float4*)&BsH[brow][bcol] = h0;
            *(float4*)&BsL[brow][bcol] = l0;
        }
        __syncthreads();

        if (t + 1 < TT) {
            int ko = (t + 1) * 16;
            ra0 = *(const float4*)(Ap + ko);
            ra1 = *(const float4*)(Ap + ko + 4);
            rb0 = *(const float4*)(Bp + (size_t)ko * T3);
        }

        #pragma unroll
        for (int kk = 0; kk < 16; kk += 8) {
            uint32_t ahi[16], alo[16], bhi[4], blo[4];
            #pragma unroll
            for (int mf = 0; mf < 4; mf++) {
                int mb = wm + mf * 16 + g;
                ahi[mf*4+0] = __float_as_uint(AsH[kk + tg][mb]);
                alo[mf*4+0] = __float_as_uint(AsL[kk + tg][mb]);
                ahi[mf*4+1] = __float_as_uint(AsH[kk + tg][mb + 8]);
                alo[mf*4+1] = __float_as_uint(AsL[kk + tg][mb + 8]);
                ahi[mf*4+2] = __float_as_uint(AsH[kk + tg + 4][mb]);
                alo[mf*4+2] = __float_as_uint(AsL[kk + tg + 4][mb]);
                ahi[mf*4+3] = __float_as_uint(AsH[kk + tg + 4][mb + 8]);
                alo[mf*4+3] = __float_as_uint(AsL[kk + tg + 4][mb + 8]);
            }
            #pragma unroll
            for (int nf = 0; nf < 2; nf++) {
                int nb = wn + nf * 8 + g;
                bhi[nf*2+0] = __float_as_uint(BsH[kk + tg][nb]);
                blo[nf*2+0] = __float_as_uint(BsL[kk + tg][nb]);
                bhi[nf*2+1] = __float_as_uint(BsH[kk + tg + 4][nb]);
                blo[nf*2+1] = __float_as_uint(BsL[kk + tg + 4][nb]);
            }
            #pragma unroll
            for (int mf = 0; mf < 4; mf++)
                #pragma unroll
                for (int nf = 0; nf < 2; nf++) {
                    float* c = acc[mf * 2 + nf];
                    mma_tf32(c, &alo[mf*4], &bhi[nf*2]);
                    mma_tf32(c, &ahi[mf*4], &blo[nf*2]);
                    mma_tf32(c, &ahi[mf*4], &bhi[nf*2]);
                }
        }
        __syncthreads();
    }

    #pragma unroll
    for (int mf = 0; mf < 4; mf++)
        #pragma unroll
        for (int nf = 0; nf < 2; nf++) {
            const float* c = acc[mf * 2 + nf];
            int mrow = m0 + wm + mf * 16 + g;
            int ncol = h * DH + wn + nf * 8 + tg * 2;
            float* o = ctx + (size_t)(b * NT + mrow) * HD + ncol;
            o[0] = c[0]; o[1] = c[1];
            o[(size_t)8 * HD] = c[2]; o[(size_t)8 * HD + 1] = c[3];
        }
}

// ---------------- softmax over key dim, with additive mask, scale=1/8 ----------------
__global__ void __launch_bounds__(128) softmax_kernel(
    float* __restrict__ scores, const int* __restrict__ amask)
{
    __shared__ float sm[4];
    int row = blockIdx.x;
    int bh  = row >> 9;
    int b   = bh / NHH;
    float* p = scores + (size_t)row * NT;
    int tid = threadIdx.x;
    float v[4]; float mx = -1e30f;
    #pragma unroll
    for (int c = 0; c < 4; c++) {
        int col = tid + c * 128;
        float madd = (1.f - (float)amask[b * NT + col]) * -1e9f;
        v[c] = p[col] * 0.125f + madd;
        mx = fmaxf(mx, v[c]);
    }
    #pragma unroll
    for (int o = 16; o; o >>= 1) mx = fmaxf(mx, __shfl_xor_sync(0xffffffffu, mx, o));
    if ((tid & 31) == 0) sm[tid >> 5] = mx;
    __syncthreads();
    mx = fmaxf(fmaxf(sm[0], sm[1]), fmaxf(sm[2], sm[3]));
    __syncthreads();
    float sum = 0.f;
    #pragma unroll
    for (int c = 0; c < 4; c++) { v[c] = __expf(v[c] - mx); sum += v[c]; }
    #pragma unroll
    for (int o = 16; o; o >>= 1) sum += __shfl_xor_sync(0xffffffffu, sum, o);
    if ((tid & 31) == 0) sm[tid >> 5] = sum;
    __syncthreads();
    sum = sm[0] + sm[1] + sm[2] + sm[3];
    float inv = 1.f / sum;
    #pragma unroll
    for (int c = 0; c < 4; c++) p[tid + c * 128] = v[c] * inv;
}

// ---------------- classifier ----------------
__global__ void __launch_bounds__(256) cls_kernel(
    const float* __restrict__ x, const float* __restrict__ W,
    const float* __restrict__ bias, float* __restrict__ out)
{
    int idx = blockIdx.x * blockDim.x + threadIdx.x;
    if (idx >= TOK * NLB) return;
    int tok = idx / NLB, n = idx % NLB;
    const float* xr = x + (size_t)tok * HD;
    float s = bias[n];
    #pragma unroll 8
    for (int k = 0; k < HD; k++) s = fmaf(xr[k], W[k * NLB + n], s);
    out[idx] = s;
}

// ---------------- CRF ----------------
__global__ void __launch_bounds__(128) crf_kernel(
    const float* __restrict__ logits, const int* __restrict__ labels,
    const int* __restrict__ amask, const float* __restrict__ startv,
    const float* __restrict__ endv, const float* __restrict__ trans,
    float* __restrict__ llh, float* __restrict__ dout)
{
    __shared__ float em[511 * NLB];
    __shared__ float tr[NLB * NLB];
    __shared__ unsigned char bp[510 * NLB];
    __shared__ float mk[511];
    __shared__ int   tg[511];
    __shared__ float sd[NLB], sv[NLB];

    int b = blockIdx.x, tid = threadIdx.x;
    const float* lp = logits + (size_t)(b * NT + 1) * NLB;
    for (int i = tid; i < 511 * NLB; i += blockDim.x) em[i] = lp[i];
    for (int i = tid; i < NLB * NLB; i += blockDim.x) tr[i] = trans[i];
    for (int i = tid; i < 511; i += blockDim.x) {
        mk[i] = (float)amask[b * NT + 1 + i];
        tg[i] = labels[b * NT + 1 + i];
    }
    __syncthreads();

    if (tid < 32) {
        int j = tid;
        float tc[NLB];
        if (j < NLB) {
            #pragma unroll
            for (int i = 0; i < NLB; i++) tc[i] = tr[i * NLB + j];
            sd[j] = startv[j] + em[j];
            sv[j] = sd[j];
        }
        __syncwarp();
        float num = 0.f; int prev = 0;
        if (j == 0) { prev = tg[0]; num = startv[prev] + em[prev]; }

        for (int s = 1; s < 511; s++) {
            float m = mk[s];
            float nd = 0.f, nv = 0.f; int bi = 0;
            if (j < NLB) {
                float e = em[s * NLB + j];
                float mx = -1e30f;
                #pragma unroll
                for (int i = 0; i < NLB; i++) { float v = sd[i] + tc[i]; mx = fmaxf(mx, v); }
                float sum = 0.f;
                #pragma unroll
                for (int i = 0; i < NLB; i++) sum += __expf(sd[i] + tc[i] - mx);
                nd = mx + __logf(sum) + e;
                float bv = -1e30f;
                #pragma unroll
                for (int i = 0; i < NLB; i++) {
                    float v = sv[i] + tc[i];
                    if (v > bv) { bv = v; bi = i; }
                }
                bp[(s - 1) * NLB + j] = (unsigned char)bi;
                nv = bv + e;
            }
            __syncwarp();
            if (j < NLB && m > 0.f) { sd[j] = nd; sv[j] = nv; }
            if (j == 0) {
                int t = tg[s];
                num += m * (tr[prev * NLB + t] + em[s * NLB + t]);
                if (m > 0.f) prev = t;
            }
            __syncwarp();
        }

        if (j == 0) {
            num += endv[prev];
            float mx = -1e30f;
            #pragma unroll
            for (int i = 0; i < NLB; i++) mx = fmaxf(mx, sd[i] + endv[i]);
            float sum = 0.f;
            #pragma unroll
            for (int i = 0; i < NLB; i++) sum += __expf(sd[i] + endv[i] - mx);
            float den = mx + __logf(sum);
            llh[b] = num - den;

            float bv = -1e30f; int last = 0;
            #pragma unroll
            for (int i = 0; i < NLB; i++) {
                float v = sv[i] + endv[i];
                if (v > bv) { bv = v; last = i; }
            }
            float* pd = dout + 1 + (size_t)b * 511;
            pd[510] = (float)last;
            for (int s = 509; s >= 0; s--) {
                last = bp[s * NLB + last];
                pd[s] = (float)last;
            }
        }
    }
}

__global__ void loss_kernel(const float* __restrict__ llh, float* __restrict__ dout)
{
    if (threadIdx.x == 0) {
        float s = 0.f;
        for (int i = 0; i < NB; i++) s += llh[i];
        dout[0] = -s / (float)NB;
    }
}

// ---------------- launcher ----------------
extern "C" void kernel_launch(void* const* d_in, const int* in_sizes, int n_in,
                              void* d_out, int out_size)
{
    (void)in_sizes; (void)n_in; (void)out_size;
    const int*   ids  = (const int*)d_in[0];
    const int*   am   = (const int*)d_in[1];
    const int*   tti  = (const int*)d_in[2];
    const int*   lab  = (const int*)d_in[3];
    const float* we   = (const float*)d_in[4];
    const float* pe   = (const float*)d_in[5];
    const float* te   = (const float*)d_in[6];
    const float* elns = (const float*)d_in[7];
    const float* elnb = (const float*)d_in[8];
    const float* Wqkv = (const float*)d_in[9];
    const float* bqkv = (const float*)d_in[10];
    const float* Wo   = (const float*)d_in[11];
    const float* bo   = (const float*)d_in[12];
    const float* l1s  = (const float*)d_in[13];
    const float* l1b  = (const float*)d_in[14];
    const float* W1   = (const float*)d_in[15];
    const float* b1   = (const float*)d_in[16];
    const float* W2   = (const float*)d_in[17];
    const float* b2   = (const float*)d_in[18];
    const float* l2s  = (const float*)d_in[19];
    const float* l2b  = (const float*)d_in[20];
    const float* Wcls = (const float*)d_in[21];
    const float* bcls = (const float*)d_in[22];
    const float* cst  = (const float*)d_in[23];
    const float* cen  = (const float*)d_in[24];
    const float* ctr  = (const float*)d_in[25];
    float* out = (float*)d_out;

    float *x, *qkv, *sc, *ctx, *y, *ff, *lg, *llh;
    cudaGetSymbolAddress((void**)&x,   g_x);
    cudaGetSymbolAddress((void**)&qkv, g_qkv);
    cudaGetSymbolAddress((void**)&sc,  g_scores);
    cudaGetSymbolAddress((void**)&ctx, g_ctx);
    cudaGetSymbolAddress((void**)&y,   g_y);
    cudaGetSymbolAddress((void**)&ff,  g_ff);
    cudaGetSymbolAddress((void**)&lg,  g_logits);
    cudaGetSymbolAddress((void**)&llh, g_llh);

    embed_ln_kernel<<<TOK, 256>>>(ids, tti, we, pe, te, elns, elnb, x);

    for (int l = 0; l < NLAY; l++) {
        gemm_tf32<0><<<dim3(T3 / 128, TOK / 128), 256>>>(
            x, Wqkv + (size_t)l * HD * T3, bqkv + (size_t)l * T3, qkv, TOK, T3, HD);
        qk_tf32<<<dim3(4, 4, NBH), 256>>>(qkv, sc);
        softmax_kernel<<<NBH * NT, 128>>>(sc, am);
        av_tf32<<<dim3(4, NBH), 256>>>(sc, qkv, ctx);
        gemm_tf32<0><<<dim3(HD / 128, TOK / 128), 256>>>(
            ctx, Wo + (size_t)l * HD * HD, bo + (size_t)l * HD, y, TOK, HD, HD);
        ln_res_kernel<<<TOK, 256>>>(x, y, l1s + (size_t)l * HD, l1b + (size_t)l * HD, x);
        gemm_tf32<1><<<dim3(DFF / 128, TOK / 128), 256>>>(
            x, W1 + (size_t)l * HD * DFF, b1 + (size_t)l * DFF, ff, TOK, DFF, HD);
        gemm_tf32<0><<<dim3(HD / 128, TOK / 128), 256>>>(
            ff, W2 + (size_t)l * DFF * HD, b2 + (size_t)l * HD, y, TOK, HD, DFF);
        ln_res_kernel<<<TOK, 256>>>(x, y, l2s + (size_t)l * HD, l2b + (size_t)l * HD, x);
    }

    cls_kernel<<<(TOK * NLB + 255) / 256, 256>>>(x, Wcls, bcls, lg);
    crf_kernel<<<NB, 128>>>(lg, lab, am, cst, cen, ctr, llh, out);
    loss_kernel<<<1, 32>>>(llh, out);
}

// round 7
// speedup vs baseline: 1.7353x; 1.7353x over previous
#include <cuda_runtime.h>
#include <cuda_fp16.h>
#include <math.h>
#include <stdint.h>

// ---------------- problem constants ----------------
#define NB   16
#define NT   512
#define TOK  (NB*NT)        // 8192 tokens
#define HD   768
#define T3   (3*HD)         // 2304
#define DFF  3072
#define NHH  12
#define DH   64
#define NLB  9
#define NBH  (NB*NHH)       // 192
#define NLAY 4

// ---------------- scratch (static device globals; no runtime alloc) ----------------
__device__ float g_x[TOK*HD];
__device__ float g_qkv[TOK*T3];
__device__ float g_scores[(size_t)NBH*NT*NT];   // 201 MB
__device__ float g_ctx[TOK*HD];
__device__ float g_y[TOK*HD];
__device__ float g_ff[TOK*DFF];
__device__ float g_logits[TOK*NLB];
__device__ float g_llh[NB];

// ---------------- helpers ----------------
__device__ __forceinline__ uint32_t s2u(const void* p) {
    uint32_t a;
    asm("{ .reg .u64 t; cvta.to.shared.u64 t, %1; cvt.u32.u64 %0, t; }" : "=r"(a) : "l"(p));
    return a;
}

// split fp32 pair into packed fp16 hi / lo half2s
__device__ __forceinline__ void splitpack(float a, float b, uint32_t& H, uint32_t& L) {
    __half2 h = __floats2half2_rn(a, b);
    float2 hf = __half22float2(h);
    __half2 l = __floats2half2_rn(a - hf.x, b - hf.y);
    H = *(uint32_t*)&h;
    L = *(uint32_t*)&l;
}
__device__ __forceinline__ void cvt8(float4 u, float4 v, uint4& H, uint4& L) {
    splitpack(u.x, u.y, H.x, L.x);
    splitpack(u.z, u.w, H.y, L.y);
    splitpack(v.x, v.y, H.z, L.z);
    splitpack(v.z, v.w, H.w, L.w);
}

__device__ __forceinline__ void ldmx4(uint32_t* r, uint32_t addr) {
    asm volatile("ldmatrix.sync.aligned.m8n8.x4.shared.b16 {%0,%1,%2,%3}, [%4];"
        : "=r"(r[0]), "=r"(r[1]), "=r"(r[2]), "=r"(r[3]) : "r"(addr));
}
__device__ __forceinline__ void ldmx2(uint32_t* r, uint32_t addr) {
    asm volatile("ldmatrix.sync.aligned.m8n8.x2.shared.b16 {%0,%1}, [%2];"
        : "=r"(r[0]), "=r"(r[1]) : "r"(addr));
}
__device__ __forceinline__ void ldmx2t(uint32_t* r, uint32_t addr) {
    asm volatile("ldmatrix.sync.aligned.m8n8.x2.trans.shared.b16 {%0,%1}, [%2];"
        : "=r"(r[0]), "=r"(r[1]) : "r"(addr));
}
__device__ __forceinline__ void mma16816(float* c, const uint32_t* a, const uint32_t* b) {
    asm volatile(
        "mma.sync.aligned.m16n8k16.row.col.f32.f16.f16.f32 "
        "{%0,%1,%2,%3}, {%4,%5,%6,%7}, {%8,%9}, {%0,%1,%2,%3};"
        : "+f"(c[0]), "+f"(c[1]), "+f"(c[2]), "+f"(c[3])
        : "r"(a[0]), "r"(a[1]), "r"(a[2]), "r"(a[3]), "r"(b[0]), "r"(b[1]));
}

__device__ __forceinline__ float gelu_tanh(float v) {
    float u = 0.7978845608028654f * (v + 0.044715f * v * v * v);
    return 0.5f * v * (1.f + tanhf(u));
}

// ================= 3xFP16 GEMM: C[M,N] = A[M,K] @ B[K,N] (+bias, EPI=1 gelu) =================
// CTA tile 128x128, K-tile 32. 8 warps as 2x4 (warp tile 64x32). K % 32 == 0.
template<int EPI>
__global__ void __launch_bounds__(256) gemm_f16(
    const float* __restrict__ A, const float* __restrict__ B,
    const float* __restrict__ bias, float* __restrict__ C,
    int M, int N, int K)
{
    __shared__ __half AsH[128][40];   // [m][k32+pad8]  row 80B
    __shared__ __half AsL[128][40];
    __shared__ __half BsH[32][136];   // [k][n128+pad8] row 272B
    __shared__ __half BsL[32][136];

    const int tid = threadIdx.x, warp = tid >> 5, lane = tid & 31;
    const int m0 = blockIdx.y * 128, n0 = blockIdx.x * 128;
    const int wm = (warp >> 2) * 64, wn = (warp & 3) * 32;
    const int g = lane >> 2, tg = lane & 3;

    // fill indices
    const int am = tid >> 1, akh = (tid & 1) * 16;
    const int bk = tid >> 3, bn = (tid & 7) * 16;
    const float* Ap = A + (size_t)(m0 + am) * K + akh;
    const float* Bp = B + n0 + bn;

    // ldmatrix lane offsets
    uint32_t asHb = s2u(&AsH[0][0]), asLb = s2u(&AsL[0][0]);
    uint32_t bsHb = s2u(&BsH[0][0]), bsLb = s2u(&BsL[0][0]);
    uint32_t aoff = (uint32_t)((wm + (lane & 15)) * 80 + (lane >> 4) * 16);
    uint32_t boff = (uint32_t)(((lane & 7) + 8 * ((lane >> 3) & 1)) * 272 + wn * 2);

    float4 ra[4], rb[4];
    #pragma unroll
    for (int i = 0; i < 4; i++) {
        ra[i] = *(const float4*)(Ap + i * 4);
        rb[i] = *(const float4*)(Bp + (size_t)(bk) * N + i * 4);
    }

    float acc[16][4];
    #pragma unroll
    for (int i = 0; i < 16; i++) { acc[i][0] = acc[i][1] = acc[i][2] = acc[i][3] = 0.f; }

    const int Tn = K >> 5;
    for (int t = 0; t < Tn; t++) {
        {
            uint4 H, L;
            cvt8(ra[0], ra[1], H, L);
            *(uint4*)&AsH[am][akh] = H; *(uint4*)&AsL[am][akh] = L;
            cvt8(ra[2], ra[3], H, L);
            *(uint4*)&AsH[am][akh + 8] = H; *(uint4*)&AsL[am][akh + 8] = L;
            cvt8(rb[0], rb[1], H, L);
            *(uint4*)&BsH[bk][bn] = H; *(uint4*)&BsL[bk][bn] = L;
            cvt8(rb[2], rb[3], H, L);
            *(uint4*)&BsH[bk][bn + 8] = H; *(uint4*)&BsL[bk][bn + 8] = L;
        }
        __syncthreads();
        if (t + 1 < Tn) {
            int k0 = (t + 1) << 5;
            #pragma unroll
            for (int i = 0; i < 4; i++) {
                ra[i] = *(const float4*)(Ap + k0 + i * 4);
                rb[i] = *(const float4*)(Bp + (size_t)(k0 + bk) * N + i * 4);
            }
        }
        #pragma unroll
        for (int kk = 0; kk < 2; kk++) {
            uint32_t aH[4][4], aL[4][4], bH[4][2], bL[4][2];
            #pragma unroll
            for (int mf = 0; mf < 4; mf++) {
                ldmx4(aH[mf], asHb + aoff + mf * 1280 + kk * 32);
                ldmx4(aL[mf], asLb + aoff + mf * 1280 + kk * 32);
            }
            #pragma unroll
            for (int nf = 0; nf < 4; nf++) {
                ldmx2t(bH[nf], bsHb + boff + nf * 16 + kk * 4352);
                ldmx2t(bL[nf], bsLb + boff + nf * 16 + kk * 4352);
            }
            #pragma unroll
            for (int mf = 0; mf < 4; mf++)
                #pragma unroll
                for (int nf = 0; nf < 4; nf++) {
                    float* c = acc[mf * 4 + nf];
                    mma16816(c, aL[mf], bH[nf]);
                    mma16816(c, aH[mf], bL[nf]);
                    mma16816(c, aH[mf], bH[nf]);
                }
        }
        __syncthreads();
    }

    #pragma unroll
    for (int mf = 0; mf < 4; mf++)
        #pragma unroll
        for (int nf = 0; nf < 4; nf++) {
            const float* c = acc[mf * 4 + nf];
            int mrow = m0 + wm + mf * 16 + g;
            int ncol = n0 + wn + nf * 8 + tg * 2;
            float b0 = bias[ncol], b1 = bias[ncol + 1];
            float v0 = c[0] + b0, v1 = c[1] + b1, v2 = c[2] + b0, v3 = c[3] + b1;
            if (EPI == 1) { v0 = gelu_tanh(v0); v1 = gelu_tanh(v1); v2 = gelu_tanh(v2); v3 = gelu_tanh(v3); }
            C[(size_t)mrow * N + ncol]           = v0;
            C[(size_t)mrow * N + ncol + 1]       = v1;
            C[(size_t)(mrow + 8) * N + ncol]     = v2;
            C[(size_t)(mrow + 8) * N + ncol + 1] = v3;
        }
}

// ================= 3xFP16 QK^T: scores[bh] = Q @ K^T =================
// Both operands [token][dh] -> [rows][k] layout; B fragment via non-trans ldmatrix.
__global__ void __launch_bounds__(256) qk_f16(
    const float* __restrict__ qkv, float* __restrict__ scores)
{
    __shared__ __half AsH[128][40], AsL[128][40];
    __shared__ __half BsH[128][40], BsL[128][40];

    const int tid = threadIdx.x, warp = tid >> 5, lane = tid & 31;
    const int bh = blockIdx.z, b = bh / NHH, h = bh % NHH;
    const int m0 = blockIdx.y * 128, n0 = blockIdx.x * 128;
    const int wm = (warp >> 2) * 64, wn = (warp & 3) * 32;
    const int g = lane >> 2, tg = lane & 3;

    const int am = tid >> 1, akh = (tid & 1) * 16;
    const float* Ap = qkv + (size_t)(b * NT + m0 + am) * T3 + h * DH;
    const float* Bp = qkv + (size_t)(b * NT + n0 + am) * T3 + HD + h * DH;

    uint32_t asHb = s2u(&AsH[0][0]), asLb = s2u(&AsL[0][0]);
    uint32_t bsHb = s2u(&BsH[0][0]), bsLb = s2u(&BsL[0][0]);
    uint32_t aoff = (uint32_t)((wm + (lane & 15)) * 80 + (lane >> 4) * 16);
    uint32_t boff = (uint32_t)((wn + (lane & 7)) * 80 + ((lane >> 3) & 1) * 16);

    float acc[16][4];
    #pragma unroll
    for (int i = 0; i < 16; i++) { acc[i][0] = acc[i][1] = acc[i][2] = acc[i][3] = 0.f; }

    #pragma unroll
    for (int t = 0; t < 2; t++) {
        int k0 = t << 5;
        {
            float4 u = *(const float4*)(Ap + k0 + akh);
            float4 v = *(const float4*)(Ap + k0 + akh + 4);
            float4 u2 = *(const float4*)(Ap + k0 + akh + 8);
            float4 v2 = *(const float4*)(Ap + k0 + akh + 12);
            uint4 H, L;
            cvt8(u, v, H, L);
            *(uint4*)&AsH[am][akh] = H; *(uint4*)&AsL[am][akh] = L;
            cvt8(u2, v2, H, L);
            *(uint4*)&AsH[am][akh + 8] = H; *(uint4*)&AsL[am][akh + 8] = L;
            u  = *(const float4*)(Bp + k0 + akh);
            v  = *(const float4*)(Bp + k0 + akh + 4);
            u2 = *(const float4*)(Bp + k0 + akh + 8);
            v2 = *(const float4*)(Bp + k0 + akh + 12);
            cvt8(u, v, H, L);
            *(uint4*)&BsH[am][akh] = H; *(uint4*)&BsL[am][akh] = L;
            cvt8(u2, v2, H, L);
            *(uint4*)&BsH[am][akh + 8] = H; *(uint4*)&BsL[am][akh + 8] = L;
        }
        __syncthreads();
        #pragma unroll
        for (int kk = 0; kk < 2; kk++) {
            uint32_t aH[4][4], aL[4][4], bH[4][2], bL[4][2];
            #pragma unroll
            for (int mf = 0; mf < 4; mf++) {
                ldmx4(aH[mf], asHb + aoff + mf * 1280 + kk * 32);
                ldmx4(aL[mf], asLb + aoff + mf * 1280 + kk * 32);
            }
            #pragma unroll
            for (int nf = 0; nf < 4; nf++) {
                ldmx2(bH[nf], bsHb + boff + nf * 640 + kk * 32);
                ldmx2(bL[nf], bsLb + boff + nf * 640 + kk * 32);
            }
            #pragma unroll
            for (int mf = 0; mf < 4; mf++)
                #pragma unroll
                for (int nf = 0; nf < 4; nf++) {
                    float* c = acc[mf * 4 + nf];
                    mma16816(c, aL[mf], bH[nf]);
                    mma16816(c, aH[mf], bL[nf]);
                    mma16816(c, aH[mf], bH[nf]);
                }
        }
        __syncthreads();
    }

    float* out = scores + (size_t)bh * NT * NT;
    #pragma unroll
    for (int mf = 0; mf < 4; mf++)
        #pragma unroll
        for (int nf = 0; nf < 4; nf++) {
            const float* c = acc[mf * 4 + nf];
            int mrow = m0 + wm + mf * 16 + g;
            int ncol = n0 + wn + nf * 8 + tg * 2;
            out[(size_t)mrow * NT + ncol]           = c[0];
            out[(size_t)mrow * NT + ncol + 1]       = c[1];
            out[(size_t)(mrow + 8) * NT + ncol]     = c[2];
            out[(size_t)(mrow + 8) * NT + ncol + 1] = c[3];
        }
}

// ================= 3xFP16 S@V: ctx = S @ V (N=64) =================
__global__ void __launch_bounds__(256) av_f16(
    const float* __restrict__ scores, const float* __restrict__ qkv, float* __restrict__ ctx)
{
    __shared__ __half AsH[128][40], AsL[128][40];
    __shared__ __half BsH[32][72], BsL[32][72];    // [k][n64+pad8] row 144B

    const int tid = threadIdx.x, warp = tid >> 5, lane = tid & 31;
    const int bh = blockIdx.y, b = bh / NHH, h = bh % NHH;
    const int m0 = blockIdx.x * 128;
    const int wm = (warp >> 2) * 64, wn = (warp & 3) * 16;
    const int g = lane >> 2, tg = lane & 3;

    const int am = tid >> 1, akh = (tid & 1) * 16;
    const float* Ap = scores + (size_t)bh * NT * NT + (size_t)(m0 + am) * NT + akh;
    const int vk = tid >> 3, vn8 = (tid & 7) * 8;
    const float* Vp = qkv + 2 * HD + h * DH + vn8;

    uint32_t asHb = s2u(&AsH[0][0]), asLb = s2u(&AsL[0][0]);
    uint32_t bsHb = s2u(&BsH[0][0]), bsLb = s2u(&BsL[0][0]);
    uint32_t aoff = (uint32_t)((wm + (lane & 15)) * 80 + (lane >> 4) * 16);
    uint32_t boff = (uint32_t)(((lane & 7) + 8 * ((lane >> 3) & 1)) * 144 + wn * 2);

    float4 ra[4]; float4 rv[2];
    #pragma unroll
    for (int i = 0; i < 4; i++) ra[i] = *(const float4*)(Ap + i * 4);
    rv[0] = *(const float4*)(Vp + (size_t)(b * NT + vk) * T3);
    rv[1] = *(const float4*)(Vp + (size_t)(b * NT + vk) * T3 + 4);

    float acc[8][4];
    #pragma unroll
    for (int i = 0; i < 8; i++) { acc[i][0] = acc[i][1] = acc[i][2] = acc[i][3] = 0.f; }

    const int Tn = NT >> 5;   // 16
    for (int t = 0; t < Tn; t++) {
        {
            uint4 H, L;
            cvt8(ra[0], ra[1], H, L);
            *(uint4*)&AsH[am][akh] = H; *(uint4*)&AsL[am][akh] = L;
            cvt8(ra[2], ra[3], H, L);
            *(uint4*)&AsH[am][akh + 8] = H; *(uint4*)&AsL[am][akh + 8] = L;
            cvt8(rv[0], rv[1], H, L);
            *(uint4*)&BsH[vk][vn8] = H; *(uint4*)&BsL[vk][vn8] = L;
        }
        __syncthreads();
        if (t + 1 < Tn) {
            int k0 = (t + 1) << 5;
            #pragma unroll
            for (int i = 0; i < 4; i++) ra[i] = *(const float4*)(Ap + k0 + i * 4);
            rv[0] = *(const float4*)(Vp + (size_t)(b * NT + k0 + vk) * T3);
            rv[1] = *(const float4*)(Vp + (size_t)(b * NT + k0 + vk) * T3 + 4);
        }
        #pragma unroll
        for (int kk = 0; kk < 2; kk++) {
            uint32_t aH[4][4], aL[4][4], bH[2][2], bL[2][2];
            #pragma unroll
            for (int mf = 0; mf < 4; mf++) {
                ldmx4(aH[mf], asHb + aoff + mf * 1280 + kk * 32);
                ldmx4(aL[mf], asLb + aoff + mf * 1280 + kk * 32);
            }
            #pragma unroll
            for (int nf = 0; nf < 2; nf++) {
                ldmx2t(bH[nf], bsHb + boff + nf * 16 + kk * 2304);
                ldmx2t(bL[nf], bsLb + boff + nf * 16 + kk * 2304);
            }
            #pragma unroll
            for (int mf = 0; mf < 4; mf++)
                #pragma unroll
                for (int nf = 0; nf < 2; nf++) {
                    float* c = acc[mf * 2 + nf];
                    mma16816(c, aL[mf], bH[nf]);
                    mma16816(c, aH[mf], bL[nf]);
                    mma16816(c, aH[mf], bH[nf]);
                }
        }
        __syncthreads();
    }

    #pragma unroll
    for (int mf = 0; mf < 4; mf++)
        #pragma unroll
        for (int nf = 0; nf < 2; nf++) {
            const float* c = acc[mf * 2 + nf];
            int mrow = m0 + wm + mf * 16 + g;
            int ncol = h * DH + wn + nf * 8 + tg * 2;
            float* o = ctx + (size_t)(b * NT + mrow) * HD + ncol;
            o[0] = c[0]; o[1] = c[1];
            o[(size_t)8 * HD] = c[2]; o[(size_t)8 * HD + 1] = c[3];
        }
}

// ---------------- reductions ----------------
__device__ __forceinline__ void reduce2_256(float& a, float& b) {
    __shared__ float sa[8], sb[8];
    #pragma unroll
    for (int o = 16; o; o >>= 1) {
        a += __shfl_xor_sync(0xffffffffu, a, o);
        b += __shfl_xor_sync(0xffffffffu, b, o);
    }
    int w = threadIdx.x >> 5;
    if ((threadIdx.x & 31) == 0) { sa[w] = a; sb[w] = b; }
    __syncthreads();
    a = 0.f; b = 0.f;
    #pragma unroll
    for (int i = 0; i < 8; i++) { a += sa[i]; b += sb[i]; }
}

// ---------------- embedding + LN ----------------
__global__ void __launch_bounds__(256) embed_ln_kernel(
    const int* __restrict__ ids, const int* __restrict__ tt,
    const float* __restrict__ we, const float* __restrict__ pe, const float* __restrict__ te,
    const float* __restrict__ sc, const float* __restrict__ bi, float* __restrict__ x)
{
    int tok = blockIdx.x;
    int t   = tok & (NT - 1);
    int tid = threadIdx.x;
    const float* w  = we + (size_t)ids[tok] * HD;
    const float* p  = pe + (size_t)t * HD;
    const float* ty = te + (size_t)tt[tok] * HD;
    float e[3]; float sum = 0.f, sq = 0.f;
    #pragma unroll
    for (int i = 0; i < 3; i++) {
        int c = tid + i * 256;
        float v = w[c] + p[c] + ty[c];
        e[i] = v; sum += v; sq += v * v;
    }
    reduce2_256(sum, sq);
    float mean = sum * (1.f / HD);
    float var  = sq * (1.f / HD) - mean * mean;
    float inv  = rsqrtf(var + 1e-12f);
    #pragma unroll
    for (int i = 0; i < 3; i++) {
        int c = tid + i * 256;
        x[(size_t)tok * HD + c] = (e[i] - mean) * inv * sc[c] + bi[c];
    }
}

// ---------------- residual + LN ----------------
__global__ void __launch_bounds__(256) ln_res_kernel(
    const float* __restrict__ xin, const float* __restrict__ y,
    const float* __restrict__ sc, const float* __restrict__ bi, float* __restrict__ xout)
{
    int tok = blockIdx.x;
    int tid = threadIdx.x;
    float e[3]; float sum = 0.f, sq = 0.f;
    #pragma unroll
    for (int i = 0; i < 3; i++) {
        int c = tid + i * 256;
        float v = xin[(size_t)tok * HD + c] + y[(size_t)tok * HD + c];
        e[i] = v; sum += v; sq += v * v;
    }
    reduce2_256(sum, sq);
    float mean = sum * (1.f / HD);
    float var  = sq * (1.f / HD) - mean * mean;
    float inv  = rsqrtf(var + 1e-12f);
    #pragma unroll
    for (int i = 0; i < 3; i++) {
        int c = tid + i * 256;
        xout[(size_t)tok * HD + c] = (e[i] - mean) * inv * sc[c] + bi[c];
    }
}

// ---------------- softmax over key dim, additive mask, scale=1/8 ----------------
__global__ void __launch_bounds__(128) softmax_kernel(
    float* __restrict__ scores, const int* __restrict__ amask)
{
    __shared__ float sm[4];
    int row = blockIdx.x;
    int bh  = row >> 9;
    int b   = bh / NHH;
    float* p = scores + (size_t)row * NT;
    int tid = threadIdx.x;
    float v[4]; float mx = -1e30f;
    #pragma unroll
    for (int c = 0; c < 4; c++) {
        int col = tid + c * 128;
        float madd = (1.f - (float)amask[b * NT + col]) * -1e9f;
        v[c] = p[col] * 0.125f + madd;
        mx = fmaxf(mx, v[c]);
    }
    #pragma unroll
    for (int o = 16; o; o >>= 1) mx = fmaxf(mx, __shfl_xor_sync(0xffffffffu, mx, o));
    if ((tid & 31) == 0) sm[tid >> 5] = mx;
    __syncthreads();
    mx = fmaxf(fmaxf(sm[0], sm[1]), fmaxf(sm[2], sm[3]));
    __syncthreads();
    float sum = 0.f;
    #pragma unroll
    for (int c = 0; c < 4; c++) { v[c] = __expf(v[c] - mx); sum += v[c]; }
    #pragma unroll
    for (int o = 16; o; o >>= 1) sum += __shfl_xor_sync(0xffffffffu, sum, o);
    if ((tid & 31) == 0) sm[tid >> 5] = sum;
    __syncthreads();
    sum = sm[0] + sm[1] + sm[2] + sm[3];
    float inv = 1.f / sum;
    #pragma unroll
    for (int c = 0; c < 4; c++) p[tid + c * 128] = v[c] * inv;
}

// ---------------- classifier ----------------
__global__ void __launch_bounds__(256) cls_kernel(
    const float* __restrict__ x, const float* __restrict__ W,
    const float* __restrict__ bias, float* __restrict__ out)
{
    int idx = blockIdx.x * blockDim.x + threadIdx.x;
    if (idx >= TOK * NLB) return;
    int tok = idx / NLB, n = idx % NLB;
    const float* xr = x + (size_t)tok * HD;
    float s = bias[n];
    #pragma unroll 8
    for (int k = 0; k < HD; k++) s = fmaf(xr[k], W[k * NLB + n], s);
    out[idx] = s;
}

// ---------------- CRF ----------------
__global__ void __launch_bounds__(128) crf_kernel(
    const float* __restrict__ logits, const int* __restrict__ labels,
    const int* __restrict__ amask, const float* __restrict__ startv,
    const float* __restrict__ endv, const float* __restrict__ trans,
    float* __restrict__ llh, float* __restrict__ dout)
{
    __shared__ float em[511 * NLB];
    __shared__ float tr[NLB * NLB];
    __shared__ unsigned char bp[510 * NLB];
    __shared__ float mk[511];
    __shared__ int   tg[511];
    __shared__ float sd[NLB], sv[NLB];

    int b = blockIdx.x, tid = threadIdx.x;
    const float* lp = logits + (size_t)(b * NT + 1) * NLB;
    for (int i = tid; i < 511 * NLB; i += blockDim.x) em[i] = lp[i];
    for (int i = tid; i < NLB * NLB; i += blockDim.x) tr[i] = trans[i];
    for (int i = tid; i < 511; i += blockDim.x) {
        mk[i] = (float)amask[b * NT + 1 + i];
        tg[i] = labels[b * NT + 1 + i];
    }
    __syncthreads();

    if (tid < 32) {
        int j = tid;
        float tc[NLB];
        if (j < NLB) {
            #pragma unroll
            for (int i = 0; i < NLB; i++) tc[i] = tr[i * NLB + j];
            sd[j] = startv[j] + em[j];
            sv[j] = sd[j];
        }
        __syncwarp();
        float num = 0.f; int prev = 0;
        if (j == 0) { prev = tg[0]; num = startv[prev] + em[prev]; }

        for (int s = 1; s < 511; s++) {
            float m = mk[s];
            float nd = 0.f, nv = 0.f; int bi = 0;
            if (j < NLB) {
                float e = em[s * NLB + j];
                float mx = -1e30f;
                #pragma unroll
                for (int i = 0; i < NLB; i++) { float v = sd[i] + tc[i]; mx = fmaxf(mx, v); }
                float sum = 0.f;
                #pragma unroll
                for (int i = 0; i < NLB; i++) sum += __expf(sd[i] + tc[i] - mx);
                nd = mx + __logf(sum) + e;
                float bv = -1e30f;
                #pragma unroll
                for (int i = 0; i < NLB; i++) {
                    float v = sv[i] + tc[i];
                    if (v > bv) { bv = v; bi = i; }
                }
                bp[(s - 1) * NLB + j] = (unsigned char)bi;
                nv = bv + e;
            }
            __syncwarp();
            if (j < NLB && m > 0.f) { sd[j] = nd; sv[j] = nv; }
            if (j == 0) {
                int t = tg[s];
                num += m * (tr[prev * NLB + t] + em[s * NLB + t]);
                if (m > 0.f) prev = t;
            }
            __syncwarp();
        }

        if (j == 0) {
            num += endv[prev];
            float mx = -1e30f;
            #pragma unroll
            for (int i = 0; i < NLB; i++) mx = fmaxf(mx, sd[i] + endv[i]);
            float sum = 0.f;
            #pragma unroll
            for (int i = 0; i < NLB; i++) sum += __expf(sd[i] + endv[i] - mx);
            float den = mx + __logf(sum);
            llh[b] = num - den;

            float bv = -1e30f; int last = 0;
            #pragma unroll
            for (int i = 0; i < NLB; i++) {
                float v = sv[i] + endv[i];
                if (v > bv) { bv = v; last = i; }
            }
            float* pd = dout + 1 + (size_t)b * 511;
            pd[510] = (float)last;
            for (int s = 509; s >= 0; s--) {
                last = bp[s * NLB + last];
                pd[s] = (float)last;
            }
        }
    }
}

__global__ void loss_kernel(const float* __restrict__ llh, float* __restrict__ dout)
{
    if (threadIdx.x == 0) {
        float s = 0.f;
        for (int i = 0; i < NB; i++) s += llh[i];
        dout[0] = -s / (float)NB;
    }
}

// ---------------- launcher ----------------
extern "C" void kernel_launch(void* const* d_in, const int* in_sizes, int n_in,
                              void* d_out, int out_size)
{
    (void)in_sizes; (void)n_in; (void)out_size;
    const int*   ids  = (const int*)d_in[0];
    const int*   am   = (const int*)d_in[1];
    const int*   tti  = (const int*)d_in[2];
    const int*   lab  = (const int*)d_in[3];
    const float* we   = (const float*)d_in[4];
    const float* pe   = (const float*)d_in[5];
    const float* te   = (const float*)d_in[6];
    const float* elns = (const float*)d_in[7];
    const float* elnb = (const float*)d_in[8];
    const float* Wqkv = (const float*)d_in[9];
    const float* bqkv = (const float*)d_in[10];
    const float* Wo   = (const float*)d_in[11];
    const float* bo   = (const float*)d_in[12];
    const float* l1s  = (const float*)d_in[13];
    const float* l1b  = (const float*)d_in[14];
    const float* W1   = (const float*)d_in[15];
    const float* b1   = (const float*)d_in[16];
    const float* W2   = (const float*)d_in[17];
    const float* b2   = (const float*)d_in[18];
    const float* l2s  = (const float*)d_in[19];
    const float* l2b  = (const float*)d_in[20];
    const float* Wcls = (const float*)d_in[21];
    const float* bcls = (const float*)d_in[22];
    const float* cst  = (const float*)d_in[23];
    const float* cen  = (const float*)d_in[24];
    const float* ctr  = (const float*)d_in[25];
    float* out = (float*)d_out;

    float *x, *qkv, *sc, *ctx, *y, *ff, *lg, *llh;
    cudaGetSymbolAddress((void**)&x,   g_x);
    cudaGetSymbolAddress((void**)&qkv, g_qkv);
    cudaGetSymbolAddress((void**)&sc,  g_scores);
    cudaGetSymbolAddress((void**)&ctx, g_ctx);
    cudaGetSymbolAddress((void**)&y,   g_y);
    cudaGetSymbolAddress((void**)&ff,  g_ff);
    cudaGetSymbolAddress((void**)&lg,  g_logits);
    cudaGetSymbolAddress((void**)&llh, g_llh);

    embed_ln_kernel<<<TOK, 256>>>(ids, tti, we, pe, te, elns, elnb, x);

    for (int l = 0; l < NLAY; l++) {
        gemm_f16<0><<<dim3(T3 / 128, TOK / 128), 256>>>(
            x, Wqkv + (size_t)l * HD * T3, bqkv + (size_t)l * T3, qkv, TOK, T3, HD);
        qk_f16<<<dim3(4, 4, NBH), 256>>>(qkv, sc);
        softmax_kernel<<<NBH * NT, 128>>>(sc, am);
        av_f16<<<dim3(4, NBH), 256>>>(sc, qkv, ctx);
        gemm_f16<0><<<dim3(HD / 128, TOK / 128), 256>>>(
            ctx, Wo + (size_t)l * HD * HD, bo + (size_t)l * HD, y, TOK, HD, HD);
        ln_res_kernel<<<TOK, 256>>>(x, y, l1s + (size_t)l * HD, l1b + (size_t)l * HD, x);
        gemm_f16<1><<<dim3(DFF / 128, TOK / 128), 256>>>(
            x, W1 + (size_t)l * HD * DFF, b1 + (size_t)l * DFF, ff, TOK, DFF, HD);
        gemm_f16<0><<<dim3(HD / 128, TOK / 128), 256>>>(
            ff, W2 + (size_t)l * DFF * HD, b2 + (size_t)l * HD, y, TOK, HD, DFF);
        ln_res_kernel<<<TOK, 256>>>(x, y, l2s + (size_t)l * HD, l2b + (size_t)l * HD, x);
    }

    cls_kernel<<<(TOK * NLB + 255) / 256, 256>>>(x, Wcls, bcls, lg);
    crf_kernel<<<NB, 128>>>(lg, lab, am, cst, cen, ctr, llh, out);
    loss_kernel<<<1, 32>>>(llh, out);
}

// round 9
// speedup vs baseline: 1.8668x; 1.0758x over previous
#include <cuda_runtime.h>
#include <cuda_fp16.h>
#include <math.h>
#include <stdint.h>

// ---------------- problem constants ----------------
#define NB   16
#define NT   512
#define TOK  (NB*NT)        // 8192 tokens
#define HD   768
#define T3   (3*HD)         // 2304
#define DFF  3072
#define NHH  12
#define DH   64
#define NLB  9
#define NBH  (NB*NHH)       // 192
#define NLAY 4

// ---------------- scratch (static device globals; no runtime alloc) ----------------
__device__ float g_x[TOK*HD];
__device__ float g_scores[(size_t)NBH*NT*NT];   // 201 MB fp32 (qk -> softmax)
__device__ float g_y[TOK*HD];
__device__ float g_logits[TOK*NLB];
__device__ float g_llh[NB];

__device__ __half g_xh[TOK*HD],   g_xl[TOK*HD];
__device__ __half g_qkvh[TOK*T3], g_qkvl[TOK*T3];
__device__ __half g_sh[(size_t)NBH*NT*NT], g_sl[(size_t)NBH*NT*NT];
__device__ __half g_ctxh[TOK*HD], g_ctxl[TOK*HD];
__device__ __half g_ffh[TOK*DFF], g_ffl[TOK*DFF];
__device__ __half g_wqh[NLAY*HD*T3],  g_wql[NLAY*HD*T3];
__device__ __half g_woh[NLAY*HD*HD],  g_wol[NLAY*HD*HD];
__device__ __half g_w1h[NLAY*HD*DFF], g_w1l[NLAY*HD*DFF];
__device__ __half g_w2h[NLAY*DFF*HD], g_w2l[NLAY*DFF*HD];

// ---------------- helpers ----------------
__device__ __forceinline__ uint32_t s2u(const void* p) {
    uint32_t a;
    asm("{ .reg .u64 t; cvta.to.shared.u64 t, %1; cvt.u32.u64 %0, t; }" : "=r"(a) : "l"(p));
    return a;
}
__device__ __forceinline__ void splitpack(float a, float b, uint32_t& H, uint32_t& L) {
    __half2 h = __floats2half2_rn(a, b);
    float2 hf = __half22float2(h);
    __half2 l = __floats2half2_rn(a - hf.x, b - hf.y);
    H = *(uint32_t*)&h;
    L = *(uint32_t*)&l;
}
__device__ __forceinline__ void ldmx4(uint32_t* r, uint32_t addr) {
    asm volatile("ldmatrix.sync.aligned.m8n8.x4.shared.b16 {%0,%1,%2,%3}, [%4];"
        : "=r"(r[0]), "=r"(r[1]), "=r"(r[2]), "=r"(r[3]) : "r"(addr));
}
__device__ __forceinline__ void ldmx2(uint32_t* r, uint32_t addr) {
    asm volatile("ldmatrix.sync.aligned.m8n8.x2.shared.b16 {%0,%1}, [%2];"
        : "=r"(r[0]), "=r"(r[1]) : "r"(addr));
}
__device__ __forceinline__ void ldmx2t(uint32_t* r, uint32_t addr) {
    asm volatile("ldmatrix.sync.aligned.m8n8.x2.trans.shared.b16 {%0,%1}, [%2];"
        : "=r"(r[0]), "=r"(r[1]) : "r"(addr));
}
__device__ __forceinline__ void mma16816(float* c, const uint32_t* a, const uint32_t* b) {
    asm volatile(
        "mma.sync.aligned.m16n8k16.row.col.f32.f16.f16.f32 "
        "{%0,%1,%2,%3}, {%4,%5,%6,%7}, {%8,%9}, {%0,%1,%2,%3};"
        : "+f"(c[0]), "+f"(c[1]), "+f"(c[2]), "+f"(c[3])
        : "r"(a[0]), "r"(a[1]), "r"(a[2]), "r"(a[3]), "r"(b[0]), "r"(b[1]));
}
__device__ __forceinline__ float gelu_tanh(float v) {
    float u = 0.7978845608028654f * (v + 0.044715f * v * v * v);
    return 0.5f * v * (1.f + tanhf(u));
}

// ---------------- fp32 -> split half (weights) ----------------
__global__ void __launch_bounds__(256) split_kernel(
    const float* __restrict__ s, __half* __restrict__ h, __half* __restrict__ l, int n)
{
    int i = (blockIdx.x * blockDim.x + threadIdx.x) * 4;
    if (i >= n) return;
    float4 v = *(const float4*)(s + i);
    uint32_t H0, L0, H1, L1;
    splitpack(v.x, v.y, H0, L0);
    splitpack(v.z, v.w, H1, L1);
    *(uint32_t*)(h + i) = H0; *(uint32_t*)(h + i + 2) = H1;
    *(uint32_t*)(l + i) = L0; *(uint32_t*)(l + i + 2) = L1;
}

// ================= 3xFP16 GEMM on pre-split halves =================
// C = A @ B + bias.  EPI: 0 -> fp32 C; 1 -> half CH/CL + gelu; 2 -> half CH/CL.
// CTA 128x128, K-tile 32, 8 warps as 2x4 (warp 64x32). K % 32 == 0.
template<int EPI>
__global__ void __launch_bounds__(256) gemm_h(
    const __half* __restrict__ AH, const __half* __restrict__ AL,
    const __half* __restrict__ BH, const __half* __restrict__ BL,
    const float* __restrict__ bias,
    float* __restrict__ Cf, __half* __restrict__ CH, __half* __restrict__ CL,
    int M, int N, int K)
{
    __shared__ __half AsH[128][40], AsL[128][40];    // [m][k32+8] row 80B
    __shared__ __half BsH[32][136], BsL[32][136];    // [k][n128+8] row 272B

    const int tid = threadIdx.x, warp = tid >> 5, lane = tid & 31;
    const int m0 = blockIdx.y * 128, n0 = blockIdx.x * 128;
    const int wm = (warp >> 2) * 64, wn = (warp & 3) * 32;
    const int g = lane >> 2, tg = lane & 3;

    const int am = tid >> 1, ac = (tid & 1) * 16;
    const int bk = tid >> 3, bn = (tid & 7) * 16;
    const __half* AHp = AH + (size_t)(m0 + am) * K + ac;
    const __half* ALp = AL + (size_t)(m0 + am) * K + ac;
    const __half* BHp = BH + n0 + bn;
    const __half* BLp = BL + n0 + bn;

    uint32_t asHb = s2u(&AsH[0][0]), asLb = s2u(&AsL[0][0]);
    uint32_t bsHb = s2u(&BsH[0][0]), bsLb = s2u(&BsL[0][0]);
    uint32_t aoff = (uint32_t)((wm + (lane & 15)) * 80 + (lane >> 4) * 16);
    uint32_t boff = (uint32_t)(((lane & 7) + 8 * ((lane >> 3) & 1)) * 272 + wn * 2);

    uint4 rah[2], ral[2], rbh[2], rbl[2];
    rah[0] = *(const uint4*)(AHp);     rah[1] = *(const uint4*)(AHp + 8);
    ral[0] = *(const uint4*)(ALp);     ral[1] = *(const uint4*)(ALp + 8);
    rbh[0] = *(const uint4*)(BHp + (size_t)bk * N);
    rbh[1] = *(const uint4*)(BHp + (size_t)bk * N + 8);
    rbl[0] = *(const uint4*)(BLp + (size_t)bk * N);
    rbl[1] = *(const uint4*)(BLp + (size_t)bk * N + 8);

    float acc[16][4];
    #pragma unroll
    for (int i = 0; i < 16; i++) { acc[i][0] = acc[i][1] = acc[i][2] = acc[i][3] = 0.f; }

    const int Tn = K >> 5;
    for (int t = 0; t < Tn; t++) {
        *(uint4*)&AsH[am][ac] = rah[0]; *(uint4*)&AsH[am][ac + 8] = rah[1];
        *(uint4*)&AsL[am][ac] = ral[0]; *(uint4*)&AsL[am][ac + 8] = ral[1];
        *(uint4*)&BsH[bk][bn] = rbh[0]; *(uint4*)&BsH[bk][bn + 8] = rbh[1];
        *(uint4*)&BsL[bk][bn] = rbl[0]; *(uint4*)&BsL[bk][bn + 8] = rbl[1];
        __syncthreads();
        if (t + 1 < Tn) {
            int k0 = (t + 1) << 5;
            rah[0] = *(const uint4*)(AHp + k0);     rah[1] = *(const uint4*)(AHp + k0 + 8);
            ral[0] = *(const uint4*)(ALp + k0);     ral[1] = *(const uint4*)(ALp + k0 + 8);
            rbh[0] = *(const uint4*)(BHp + (size_t)(k0 + bk) * N);
            rbh[1] = *(const uint4*)(BHp + (size_t)(k0 + bk) * N + 8);
            rbl[0] = *(const uint4*)(BLp + (size_t)(k0 + bk) * N);
            rbl[1] = *(const uint4*)(BLp + (size_t)(k0 + bk) * N + 8);
        }
        #pragma unroll
        for (int kk = 0; kk < 2; kk++) {
            uint32_t aH[4][4], aL[4][4], bH[4][2], bL[4][2];
            #pragma unroll
            for (int mf = 0; mf < 4; mf++) {
                ldmx4(aH[mf], asHb + aoff + mf * 1280 + kk * 32);
                ldmx4(aL[mf], asLb + aoff + mf * 1280 + kk * 32);
            }
            #pragma unroll
            for (int nf = 0; nf < 4; nf++) {
                ldmx2t(bH[nf], bsHb + boff + nf * 16 + kk * 4352);
                ldmx2t(bL[nf], bsLb + boff + nf * 16 + kk * 4352);
            }
            #pragma unroll
            for (int mf = 0; mf < 4; mf++)
                #pragma unroll
                for (int nf = 0; nf < 4; nf++) {
                    float* c = acc[mf * 4 + nf];
                    mma16816(c, aL[mf], bH[nf]);
                    mma16816(c, aH[mf], bL[nf]);
                    mma16816(c, aH[mf], bH[nf]);
                }
        }
        __syncthreads();
    }

    #pragma unroll
    for (int mf = 0; mf < 4; mf++)
        #pragma unroll
        for (int nf = 0; nf < 4; nf++) {
            const float* c = acc[mf * 4 + nf];
            int mrow = m0 + wm + mf * 16 + g;
            int ncol = n0 + wn + nf * 8 + tg * 2;
            float b0 = bias[ncol], b1 = bias[ncol + 1];
            float v0 = c[0] + b0, v1 = c[1] + b1, v2 = c[2] + b0, v3 = c[3] + b1;
            if (EPI == 1) { v0 = gelu_tanh(v0); v1 = gelu_tanh(v1); v2 = gelu_tanh(v2); v3 = gelu_tanh(v3); }
            if (EPI == 0) {
                Cf[(size_t)mrow * N + ncol]           = v0;
                Cf[(size_t)mrow * N + ncol + 1]       = v1;
                Cf[(size_t)(mrow + 8) * N + ncol]     = v2;
                Cf[(size_t)(mrow + 8) * N + ncol + 1] = v3;
            } else {
                uint32_t H, L;
                splitpack(v0, v1, H, L);
                *(uint32_t*)&CH[(size_t)mrow * N + ncol] = H;
                *(uint32_t*)&CL[(size_t)mrow * N + ncol] = L;
                splitpack(v2, v3, H, L);
                *(uint32_t*)&CH[(size_t)(mrow + 8) * N + ncol] = H;
                *(uint32_t*)&CL[(size_t)(mrow + 8) * N + ncol] = L;
            }
        }
}

// ================= 3xFP16 QK^T on pre-split qkv =================
__global__ void __launch_bounds__(256) qk_h(
    const __half* __restrict__ QKVH, const __half* __restrict__ QKVL,
    float* __restrict__ scores)
{
    __shared__ __half AsH[128][40], AsL[128][40];
    __shared__ __half BsH[128][40], BsL[128][40];

    const int tid = threadIdx.x, warp = tid >> 5, lane = tid & 31;
    const int bh = blockIdx.z, b = bh / NHH, h = bh % NHH;
    const int m0 = blockIdx.y * 128, n0 = blockIdx.x * 128;
    const int wm = (warp >> 2) * 64, wn = (warp & 3) * 32;
    const int g = lane >> 2, tg = lane & 3;

    const int am = tid >> 1, ac = (tid & 1) * 16;
    const __half* AHp = QKVH + (size_t)(b * NT + m0 + am) * T3 + h * DH + ac;
    const __half* ALp = QKVL + (size_t)(b * NT + m0 + am) * T3 + h * DH + ac;
    const __half* BHp = QKVH + (size_t)(b * NT + n0 + am) * T3 + HD + h * DH + ac;
    const __half* BLp = QKVL + (size_t)(b * NT + n0 + am) * T3 + HD + h * DH + ac;

    uint32_t asHb = s2u(&AsH[0][0]), asLb = s2u(&AsL[0][0]);
    uint32_t bsHb = s2u(&BsH[0][0]), bsLb = s2u(&BsL[0][0]);
    uint32_t aoff = (uint32_t)((wm + (lane & 15)) * 80 + (lane >> 4) * 16);
    uint32_t boff = (uint32_t)((wn + (lane & 7)) * 80 + ((lane >> 3) & 1) * 16);

    float acc[16][4];
    #pragma unroll
    for (int i = 0; i < 16; i++) { acc[i][0] = acc[i][1] = acc[i][2] = acc[i][3] = 0.f; }

    #pragma unroll
    for (int t = 0; t < 2; t++) {
        int k0 = t << 5;
        *(uint4*)&AsH[am][ac] = *(const uint4*)(AHp + k0);
        *(uint4*)&AsH[am][ac + 8] = *(const uint4*)(AHp + k0 + 8);
        *(uint4*)&AsL[am][ac] = *(const uint4*)(ALp + k0);
        *(uint4*)&AsL[am][ac + 8] = *(const uint4*)(ALp + k0 + 8);
        *(uint4*)&BsH[am][ac] = *(const uint4*)(BHp + k0);
        *(uint4*)&BsH[am][ac + 8] = *(const uint4*)(BHp + k0 + 8);
        *(uint4*)&BsL[am][ac] = *(const uint4*)(BLp + k0);
        *(uint4*)&BsL[am][ac + 8] = *(const uint4*)(BLp + k0 + 8);
        __syncthreads();
        #pragma unroll
        for (int kk = 0; kk < 2; kk++) {
            uint32_t aH[4][4], aL[4][4], bH[4][2], bL[4][2];
            #pragma unroll
            for (int mf = 0; mf < 4; mf++) {
                ldmx4(aH[mf], asHb + aoff + mf * 1280 + kk * 32);
                ldmx4(aL[mf], asLb + aoff + mf * 1280 + kk * 32);
            }
            #pragma unroll
            for (int nf = 0; nf < 4; nf++) {
                ldmx2(bH[nf], bsHb + boff + nf * 640 + kk * 32);
                ldmx2(bL[nf], bsLb + boff + nf * 640 + kk * 32);
            }
            #pragma unroll
            for (int mf = 0; mf < 4; mf++)
                #pragma unroll
                for (int nf = 0; nf < 4; nf++) {
                    float* c = acc[mf * 4 + nf];
                    mma16816(c, aL[mf], bH[nf]);
                    mma16816(c, aH[mf], bL[nf]);
                    mma16816(c, aH[mf], bH[nf]);
                }
        }
        __syncthreads();
    }

    float* out = scores + (size_t)bh * NT * NT;
    #pragma unroll
    for (int mf = 0; mf < 4; mf++)
        #pragma unroll
        for (int nf = 0; nf < 4; nf++) {
            const float* c = acc[mf * 4 + nf];
            int mrow = m0 + wm + mf * 16 + g;
            int ncol = n0 + wn + nf * 8 + tg * 2;
            out[(size_t)mrow * NT + ncol]           = c[0];
            out[(size_t)mrow * NT + ncol + 1]       = c[1];
            out[(size_t)(mrow + 8) * NT + ncol]     = c[2];
            out[(size_t)(mrow + 8) * NT + ncol + 1] = c[3];
        }
}

// ================= 3xFP16 S@V on pre-split halves (N=64) =================
__global__ void __launch_bounds__(256) av_h(
    const __half* __restrict__ SH, const __half* __restrict__ SL,
    const __half* __restrict__ QKVH, const __half* __restrict__ QKVL,
    __half* __restrict__ CTXH, __half* __restrict__ CTXL)
{
    __shared__ __half AsH[128][40], AsL[128][40];
    __shared__ __half BsH[32][72], BsL[32][72];    // [k][n64+8] row 144B

    const int tid = threadIdx.x, warp = tid >> 5, lane = tid & 31;
    const int bh = blockIdx.y, b = bh / NHH, h = bh % NHH;
    const int m0 = blockIdx.x * 128;
    const int wm = (warp >> 2) * 64, wn = (warp & 3) * 16;
    const int g = lane >> 2, tg = lane & 3;

    const int am = tid >> 1, ac = (tid & 1) * 16;
    const __half* AHp = SH + (size_t)bh * NT * NT + (size_t)(m0 + am) * NT + ac;
    const __half* ALp = SL + (size_t)bh * NT * NT + (size_t)(m0 + am) * NT + ac;
    const int vk = tid >> 3, vn8 = (tid & 7) * 8;
    const __half* VHp = QKVH + 2 * HD + h * DH + vn8;
    const __half* VLp = QKVL + 2 * HD + h * DH + vn8;

    uint32_t asHb = s2u(&AsH[0][0]), asLb = s2u(&AsL[0][0]);
    uint32_t bsHb = s2u(&BsH[0][0]), bsLb = s2u(&BsL[0][0]);
    uint32_t aoff = (uint32_t)((wm + (lane & 15)) * 80 + (lane >> 4) * 16);
    uint32_t boff = (uint32_t)(((lane & 7) + 8 * ((lane >> 3) & 1)) * 144 + wn * 2);

    uint4 rah[2], ral[2], rvh, rvl;
    rah[0] = *(const uint4*)(AHp); rah[1] = *(const uint4*)(AHp + 8);
    ral[0] = *(const uint4*)(ALp); ral[1] = *(const uint4*)(ALp + 8);
    rvh = *(const uint4*)(VHp + (size_t)(b * NT + vk) * T3);
    rvl = *(const uint4*)(VLp + (size_t)(b * NT + vk) * T3);

    float acc[8][4];
    #pragma unroll
    for (int i = 0; i < 8; i++) { acc[i][0] = acc[i][1] = acc[i][2] = acc[i][3] = 0.f; }

    const int Tn = NT >> 5;   // 16
    for (int t = 0; t < Tn; t++) {
        *(uint4*)&AsH[am][ac] = rah[0]; *(uint4*)&AsH[am][ac + 8] = rah[1];
        *(uint4*)&AsL[am][ac] = ral[0]; *(uint4*)&AsL[am][ac + 8] = ral[1];
        *(uint4*)&BsH[vk][vn8] = rvh;   *(uint4*)&BsL[vk][vn8] = rvl;
        __syncthreads();
        if (t + 1 < Tn) {
            int k0 = (t + 1) << 5;
            rah[0] = *(const uint4*)(AHp + k0); rah[1] = *(const uint4*)(AHp + k0 + 8);
            ral[0] = *(const uint4*)(ALp + k0); ral[1] = *(const uint4*)(ALp + k0 + 8);
            rvh = *(const uint4*)(VHp + (size_t)(b * NT + k0 + vk) * T3);
            rvl = *(const uint4*)(VLp + (size_t)(b * NT + k0 + vk) * T3);
        }
        #pragma unroll
        for (int kk = 0; kk < 2; kk++) {
            uint32_t aH[4][4], aL[4][4], bH[2][2], bL[2][2];
            #pragma unroll
            for (int mf = 0; mf < 4; mf++) {
                ldmx4(aH[mf], asHb + aoff + mf * 1280 + kk * 32);
                ldmx4(aL[mf], asLb + aoff + mf * 1280 + kk * 32);
            }
            #pragma unroll
            for (int nf = 0; nf < 2; nf++) {
                ldmx2t(bH[nf], bsHb + boff + nf * 16 + kk * 2304);
                ldmx2t(bL[nf], bsLb + boff + nf * 16 + kk * 2304);
            }
            #pragma unroll
            for (int mf = 0; mf < 4; mf++)
                #pragma unroll
                for (int nf = 0; nf < 2; nf++) {
                    float* c = acc[mf * 2 + nf];
                    mma16816(c, aL[mf], bH[nf]);
                    mma16816(c, aH[mf], bL[nf]);
                    mma16816(c, aH[mf], bH[nf]);
                }
        }
        __syncthreads();
    }

    #pragma unroll
    for (int mf = 0; mf < 4; mf++)
        #pragma unroll
        for (int nf = 0; nf < 2; nf++) {
            const float* c = acc[mf * 2 + nf];
            int mrow = m0 + wm + mf * 16 + g;
            int ncol = h * DH + wn + nf * 8 + tg * 2;
            uint32_t H, L;
            splitpack(c[0], c[1], H, L);
            *(uint32_t*)&CTXH[(size_t)(b * NT + mrow) * HD + ncol] = H;
            *(uint32_t*)&CTXL[(size_t)(b * NT + mrow) * HD + ncol] = L;
            splitpack(c[2], c[3], H, L);
            *(uint32_t*)&CTXH[(size_t)(b * NT + mrow + 8) * HD + ncol] = H;
            *(uint32_t*)&CTXL[(size_t)(b * NT + mrow + 8) * HD + ncol] = L;
        }
}

// ---------------- reductions ----------------
__device__ __forceinline__ void reduce2_256(float& a, float& b) {
    __shared__ float sa[8], sb[8];
    #pragma unroll
    for (int o = 16; o; o >>= 1) {
        a += __shfl_xor_sync(0xffffffffu, a, o);
        b += __shfl_xor_sync(0xffffffffu, b, o);
    }
    int w = threadIdx.x >> 5;
    if ((threadIdx.x & 31) == 0) { sa[w] = a; sb[w] = b; }
    __syncthreads();
    a = 0.f; b = 0.f;
    #pragma unroll
    for (int i = 0; i < 8; i++) { a += sa[i]; b += sb[i]; }
}

// ---------------- embedding + LN (writes fp32 x and split halves) ----------------
__global__ void __launch_bounds__(256) embed_ln_kernel(
    const int* __restrict__ ids, const int* __restrict__ tt,
    const float* __restrict__ we, const float* __restrict__ pe, const float* __restrict__ te,
    const float* __restrict__ sc, const float* __restrict__ bi,
    float* __restrict__ x, __half* __restrict__ xh, __half* __restrict__ xl)
{
    int tok = blockIdx.x;
    int t   = tok & (NT - 1);
    int tid = threadIdx.x;
    const float* w  = we + (size_t)ids[tok] * HD;
    const float* p  = pe + (size_t)t * HD;
    const float* ty = te + (size_t)tt[tok] * HD;
    float e[3]; float sum = 0.f, sq = 0.f;
    #pragma unroll
    for (int i = 0; i < 3; i++) {
        int c = tid + i * 256;
        float v = w[c] + p[c] + ty[c];
        e[i] = v; sum += v; sq += v * v;
    }
    reduce2_256(sum, sq);
    float mean = sum * (1.f / HD);
    float var  = sq * (1.f / HD) - mean * mean;
    float inv  = rsqrtf(var + 1e-12f);
    #pragma unroll
    for (int i = 0; i < 3; i++) {
        int c = tid + i * 256;
        float v = (e[i] - mean) * inv * sc[c] + bi[c];
        size_t idx = (size_t)tok * HD + c;
        x[idx] = v;
        __half h = __float2half_rn(v);
        xh[idx] = h;
        xl[idx] = __float2half_rn(v - __half2float(h));
    }
}

// ---------------- residual + LN (writes fp32 x and split halves) ----------------
__global__ void __launch_bounds__(256) ln_res_kernel(
    const float* __restrict__ xin, const float* __restrict__ y,
    const float* __restrict__ sc, const float* __restrict__ bi,
    float* __restrict__ xout, __half* __restrict__ xh, __half* __restrict__ xl)
{
    int tok = blockIdx.x;
    int tid = threadIdx.x;
    float e[3]; float sum = 0.f, sq = 0.f;
    #pragma unroll
    for (int i = 0; i < 3; i++) {
        int c = tid + i * 256;
        float v = xin[(size_t)tok * HD + c] + y[(size_t)tok * HD + c];
        e[i] = v; sum += v; sq += v * v;
    }
    reduce2_256(sum, sq);
    float mean = sum * (1.f / HD);
    float var  = sq * (1.f / HD) - mean * mean;
    float inv  = rsqrtf(var + 1e-12f);
    #pragma unroll
    for (int i = 0; i < 3; i++) {
        int c = tid + i * 256;
        float v = (e[i] - mean) * inv * sc[c] + bi[c];
        size_t idx = (size_t)tok * HD + c;
        xout[idx] = v;
        __half h = __float2half_rn(v);
        xh[idx] = h;
        xl[idx] = __float2half_rn(v - __half2float(h));
    }
}

// ---------------- softmax: fp32 scores -> split half probabilities ----------------
__global__ void __launch_bounds__(128) softmax_kernel(
    const float* __restrict__ scores, const int* __restrict__ amask,
    __half* __restrict__ sh, __half* __restrict__ sl)
{
    __shared__ float sm[4];
    int row = blockIdx.x;
    int bh  = row >> 9;
    int b   = bh / NHH;
    const float* p = scores + (size_t)row * NT;
    int tid = threadIdx.x;
    float v[4]; float mx = -1e30f;
    #pragma unroll
    for (int c = 0; c < 4; c++) {
        int col = tid + c * 128;
        float madd = (1.f - (float)amask[b * NT + col]) * -1e9f;
        v[c] = p[col] * 0.125f + madd;
        mx = fmaxf(mx, v[c]);
    }
    #pragma unroll
    for (int o = 16; o; o >>= 1) mx = fmaxf(mx, __shfl_xor_sync(0xffffffffu, mx, o));
    if ((tid & 31) == 0) sm[tid >> 5] = mx;
    __syncthreads();
    mx = fmaxf(fmaxf(sm[0], sm[1]), fmaxf(sm[2], sm[3]));
    __syncthreads();
    float sum = 0.f;
    #pragma unroll
    for (int c = 0; c < 4; c++) { v[c] = __expf(v[c] - mx); sum += v[c]; }
    #pragma unroll
    for (int o = 16; o; o >>= 1) sum += __shfl_xor_sync(0xffffffffu, sum, o);
    if ((tid & 31) == 0) sm[tid >> 5] = sum;
    __syncthreads();
    sum = sm[0] + sm[1] + sm[2] + sm[3];
    float inv = 1.f / sum;
    #pragma unroll
    for (int c = 0; c < 4; c++) {
        int col = tid + c * 128;
        float pv = v[c] * inv;
        __half h = __float2half_rn(pv);
        sh[(size_t)row * NT + col] = h;
        sl[(size_t)row * NT + col] = __float2half_rn(pv - __half2float(h));
    }
}

// ---------------- classifier ----------------
__global__ void __launch_bounds__(256) cls_kernel(
    const float* __restrict__ x, const float* __restrict__ W,
    const float* __restrict__ bias, float* __restrict__ out)
{
    int idx = blockIdx.x * blockDim.x + threadIdx.x;
    if (idx >= TOK * NLB) return;
    int tok = idx / NLB, n = idx % NLB;
    const float* xr = x + (size_t)tok * HD;
    float s = bias[n];
    #pragma unroll 8
    for (int k = 0; k < HD; k++) s = fmaf(xr[k], W[k * NLB + n], s);
    out[idx] = s;
}

// ---------------- CRF ----------------
__global__ void __launch_bounds__(128) crf_kernel(
    const float* __restrict__ logits, const int* __restrict__ labels,
    const int* __restrict__ amask, const float* __restrict__ startv,
    const float* __restrict__ endv, const float* __restrict__ trans,
    float* __restrict__ llh, float* __restrict__ dout)
{
    __shared__ float em[511 * NLB];
    __shared__ float tr[NLB * NLB];
    __shared__ unsigned char bp[510 * NLB];
    __shared__ float mk[511];
    __shared__ int   tg[511];
    __shared__ float sd[NLB], sv[NLB];

    int b = blockIdx.x, tid = threadIdx.x;
    const float* lp = logits + (size_t)(b * NT + 1) * NLB;
    for (int i = tid; i < 511 * NLB; i += blockDim.x) em[i] = lp[i];
    for (int i = tid; i < NLB * NLB; i += blockDim.x) tr[i] = trans[i];
    for (int i = tid; i < 511; i += blockDim.x) {
        mk[i] = (float)amask[b * NT + 1 + i];
        tg[i] = labels[b * NT + 1 + i];
    }
    __syncthreads();

    if (tid < 32) {
        int j = tid;
        float tc[NLB];
        if (j < NLB) {
            #pragma unroll
            for (int i = 0; i < NLB; i++) tc[i] = tr[i * NLB + j];
            sd[j] = startv[j] + em[j];
            sv[j] = sd[j];
        }
        __syncwarp();
        float num = 0.f; int prev = 0;
        if (j == 0) { prev = tg[0]; num = startv[prev] + em[prev]; }

        for (int s = 1; s < 511; s++) {
            float m = mk[s];
            float nd = 0.f, nv = 0.f; int bi = 0;
            if (j < NLB) {
                float e = em[s * NLB + j];
                float mx = -1e30f;
                #pragma unroll
                for (int i = 0; i < NLB; i++) { float v = sd[i] + tc[i]; mx = fmaxf(mx, v); }
                float sum = 0.f;
                #pragma unroll
                for (int i = 0; i < NLB; i++) sum += __expf(sd[i] + tc[i] - mx);
                nd = mx + __logf(sum) + e;
                float bv = -1e30f;
                #pragma unroll
                for (int i = 0; i < NLB; i++) {
                    float v = sv[i] + tc[i];
                    if (v > bv) { bv = v; bi = i; }
                }
                bp[(s - 1) * NLB + j] = (unsigned char)bi;
                nv = bv + e;
            }
            __syncwarp();
            if (j < NLB && m > 0.f) { sd[j] = nd; sv[j] = nv; }
            if (j == 0) {
                int t = tg[s];
                num += m * (tr[prev * NLB + t] + em[s * NLB + t]);
                if (m > 0.f) prev = t;
            }
            __syncwarp();
        }

        if (j == 0) {
            num += endv[prev];
            float mx = -1e30f;
            #pragma unroll
            for (int i = 0; i < NLB; i++) mx = fmaxf(mx, sd[i] + endv[i]);
            float sum = 0.f;
            #pragma unroll
            for (int i = 0; i < NLB; i++) sum += __expf(sd[i] + endv[i] - mx);
            float den = mx + __logf(sum);
            llh[b] = num - den;

            float bv = -1e30f; int last = 0;
            #pragma unroll
            for (int i = 0; i < NLB; i++) {
                float v = sv[i] + endv[i];
                if (v > bv) { bv = v; last = i; }
            }
            float* pd = dout + 1 + (size_t)b * 511;
            pd[510] = (float)last;
            for (int s = 509; s >= 0; s--) {
                last = bp[s * NLB + last];
                pd[s] = (float)last;
            }
        }
    }
}

__global__ void loss_kernel(const float* __restrict__ llh, float* __restrict__ dout)
{
    if (threadIdx.x == 0) {
        float s = 0.f;
        for (int i = 0; i < NB; i++) s += llh[i];
        dout[0] = -s / (float)NB;
    }
}

// ---------------- launcher ----------------
extern "C" void kernel_launch(void* const* d_in, const int* in_sizes, int n_in,
                              void* d_out, int out_size)
{
    (void)in_sizes; (void)n_in; (void)out_size;
    const int*   ids  = (const int*)d_in[0];
    const int*   am   = (const int*)d_in[1];
    const int*   tti  = (const int*)d_in[2];
    const int*   lab  = (const int*)d_in[3];
    const float* we   = (const float*)d_in[4];
    const float* pe   = (const float*)d_in[5];
    const float* te   = (const float*)d_in[6];
    const float* elns = (const float*)d_in[7];
    const float* elnb = (const float*)d_in[8];
    const float* Wqkv = (const float*)d_in[9];
    const float* bqkv = (const float*)d_in[10];
    const float* Wo   = (const float*)d_in[11];
    const float* bo   = (const float*)d_in[12];
    const float* l1s  = (const float*)d_in[13];
    const float* l1b  = (const float*)d_in[14];
    const float* W1   = (const float*)d_in[15];
    const float* b1   = (const float*)d_in[16];
    const float* W2   = (const float*)d_in[17];
    const float* b2   = (const float*)d_in[18];
    const float* l2s  = (const float*)d_in[19];
    const float* l2b  = (const float*)d_in[20];
    const float* Wcls = (const float*)d_in[21];
    const float* bcls = (const float*)d_in[22];
    const float* cst  = (const float*)d_in[23];
    const float* cen  = (const float*)d_in[24];
    const float* ctr  = (const float*)d_in[25];
    float* out = (float*)d_out;

    float *x, *sc, *y, *lg, *llh;
    __half *xh, *xl, *qkvh, *qkvl, *sh, *sl, *ctxh, *ctxl, *ffh, *ffl;
    __half *wqh, *wql, *woh, *wol, *w1h, *w1l, *w2h, *w2l;
    cudaGetSymbolAddress((void**)&x,   g_x);
    cudaGetSymbolAddress((void**)&sc,  g_scores);
    cudaGetSymbolAddress((void**)&y,   g_y);
    cudaGetSymbolAddress((void**)&lg,  g_logits);
    cudaGetSymbolAddress((void**)&llh, g_llh);
    cudaGetSymbolAddress((void**)&xh,   g_xh);   cudaGetSymbolAddress((void**)&xl,   g_xl);
    cudaGetSymbolAddress((void**)&qkvh, g_qkvh); cudaGetSymbolAddress((void**)&qkvl, g_qkvl);
    cudaGetSymbolAddress((void**)&sh,   g_sh);   cudaGetSymbolAddress((void**)&sl,   g_sl);
    cudaGetSymbolAddress((void**)&ctxh, g_ctxh); cudaGetSymbolAddress((void**)&ctxl, g_ctxl);
    cudaGetSymbolAddress((void**)&ffh,  g_ffh);  cudaGetSymbolAddress((void**)&ffl,  g_ffl);
    cudaGetSymbolAddress((void**)&wqh,  g_wqh);  cudaGetSymbolAddress((void**)&wql,  g_wql);
    cudaGetSymbolAddress((void**)&woh,  g_woh);  cudaGetSymbolAddress((void**)&wol,  g_wol);
    cudaGetSymbolAddress((void**)&w1h,  g_w1h);  cudaGetSymbolAddress((void**)&w1l,  g_w1l);
    cudaGetSymbolAddress((void**)&w2h,  g_w2h);  cudaGetSymbolAddress((void**)&w2l,  g_w2l);

    // weight splits (once per launch)
    {
        int n;
        n = NLAY * HD * T3;  split_kernel<<<(n / 4 + 255) / 256, 256>>>(Wqkv, wqh, wql, n);
        n = NLAY * HD * HD;  split_kernel<<<(n / 4 + 255) / 256, 256>>>(Wo,   woh, wol, n);
        n = NLAY * HD * DFF; split_kernel<<<(n / 4 + 255) / 256, 256>>>(W1,   w1h, w1l, n);
        n = NLAY * DFF * HD; split_kernel<<<(n / 4 + 255) / 256, 256>>>(W2,   w2h, w2l, n);
    }

    embed_ln_kernel<<<TOK, 256>>>(ids, tti, we, pe, te, elns, elnb, x, xh, xl);

    for (int l = 0; l < NLAY; l++) {
        gemm_h<2><<<dim3(T3 / 128, TOK / 128), 256>>>(
            xh, xl, wqh + (size_t)l * HD * T3, wql + (size_t)l * HD * T3,
            bqkv + (size_t)l * T3, nullptr, qkvh, qkvl, TOK, T3, HD);
        qk_h<<<dim3(4, 4, NBH), 256>>>(qkvh, qkvl, sc);
        softmax_kernel<<<NBH * NT, 128>>>(sc, am, sh, sl);
        av_h<<<dim3(4, NBH), 256>>>(sh, sl, qkvh, qkvl, ctxh, ctxl);
        gemm_h<0><<<dim3(HD / 128, TOK / 128), 256>>>(
            ctxh, ctxl, woh + (size_t)l * HD * HD, wol + (size_t)l * HD * HD,
            bo + (size_t)l * HD, y, nullptr, nullptr, TOK, HD, HD);
        ln_res_kernel<<<TOK, 256>>>(x, y, l1s + (size_t)l * HD, l1b + (size_t)l * HD, x, xh, xl);
        gemm_h<1><<<dim3(DFF / 128, TOK / 128), 256>>>(
            xh, xl, w1h + (size_t)l * HD * DFF, w1l + (size_t)l * HD * DFF,
            b1 + (size_t)l * DFF, nullptr, ffh, ffl, TOK, DFF, HD);
        gemm_h<0><<<dim3(HD / 128, TOK / 128), 256>>>(
            ffh, ffl, w2h + (size_t)l * DFF * HD, w2l + (size_t)l * DFF * HD,
            b2 + (size_t)l * HD, y, nullptr, nullptr, TOK, HD, DFF);
        ln_res_kernel<<<TOK, 256>>>(x, y, l2s + (size_t)l * HD, l2b + (size_t)l * HD, x, xh, xl);
    }

    cls_kernel<<<(TOK * NLB + 255) / 256, 256>>>(x, Wcls, bcls, lg);
    crf_kernel<<<NB, 128>>>(lg, lab, am, cst, cen, ctr, llh, out);
    loss_kernel<<<1, 32>>>(llh, out);
}

// round 11
// speedup vs baseline: 2.0759x; 1.1120x over previous
#include <cuda_runtime.h>
#include <cuda_fp16.h>
#include <math.h>
#include <stdint.h>

// ---------------- problem constants ----------------
#define NB   16
#define NT   512
#define TOK  (NB*NT)        // 8192 tokens
#define HD   768
#define T3   (3*HD)         // 2304
#define DFF  3072
#define NHH  12
#define DH   64
#define NLB  9
#define NBH  (NB*NHH)       // 192
#define NLAY 4

// ---------------- scratch (static device globals; no runtime alloc) ----------------
__device__ float g_x[TOK*HD];
__device__ float g_y[TOK*HD];
__device__ float g_logits[TOK*NLB];
__device__ float g_llh[NB];

__device__ __half g_xh[TOK*HD],   g_xl[TOK*HD];
__device__ __half g_qkvh[TOK*T3], g_qkvl[TOK*T3];
__device__ __half g_ctxh[TOK*HD], g_ctxl[TOK*HD];
__device__ __half g_ffh[TOK*DFF], g_ffl[TOK*DFF];
__device__ __half g_wqh[NLAY*HD*T3],  g_wql[NLAY*HD*T3];
__device__ __half g_woh[NLAY*HD*HD],  g_wol[NLAY*HD*HD];
__device__ __half g_w1h[NLAY*HD*DFF], g_w1l[NLAY*HD*DFF];
__device__ __half g_w2h[NLAY*DFF*HD], g_w2l[NLAY*DFF*HD];

// ---------------- helpers ----------------
__device__ __forceinline__ uint32_t s2u(const void* p) {
    uint32_t a;
    asm("{ .reg .u64 t; cvta.to.shared.u64 t, %1; cvt.u32.u64 %0, t; }" : "=r"(a) : "l"(p));
    return a;
}
__device__ __forceinline__ void splitpack(float a, float b, uint32_t& H, uint32_t& L) {
    __half2 h = __floats2half2_rn(a, b);
    float2 hf = __half22float2(h);
    __half2 l = __floats2half2_rn(a - hf.x, b - hf.y);
    H = *(uint32_t*)&h;
    L = *(uint32_t*)&l;
}
__device__ __forceinline__ void ldmx4(uint32_t* r, uint32_t addr) {
    asm volatile("ldmatrix.sync.aligned.m8n8.x4.shared.b16 {%0,%1,%2,%3}, [%4];"
        : "=r"(r[0]), "=r"(r[1]), "=r"(r[2]), "=r"(r[3]) : "r"(addr));
}
__device__ __forceinline__ void ldmx2(uint32_t* r, uint32_t addr) {
    asm volatile("ldmatrix.sync.aligned.m8n8.x2.shared.b16 {%0,%1}, [%2];"
        : "=r"(r[0]), "=r"(r[1]) : "r"(addr));
}
__device__ __forceinline__ void ldmx2t(uint32_t* r, uint32_t addr) {
    asm volatile("ldmatrix.sync.aligned.m8n8.x2.trans.shared.b16 {%0,%1}, [%2];"
        : "=r"(r[0]), "=r"(r[1]) : "r"(addr));
}
__device__ __forceinline__ void mma16816(float* c, const uint32_t* a, const uint32_t* b) {
    asm volatile(
        "mma.sync.aligned.m16n8k16.row.col.f32.f16.f16.f32 "
        "{%0,%1,%2,%3}, {%4,%5,%6,%7}, {%8,%9}, {%0,%1,%2,%3};"
        : "+f"(c[0]), "+f"(c[1]), "+f"(c[2]), "+f"(c[3])
        : "r"(a[0]), "r"(a[1]), "r"(a[2]), "r"(a[3]), "r"(b[0]), "r"(b[1]));
}
__device__ __forceinline__ float gelu_tanh(float v) {
    float u = 0.7978845608028654f * (v + 0.044715f * v * v * v);
    return 0.5f * v * (1.f + tanhf(u));
}

// ---------------- fp32 -> split half (weights) ----------------
__global__ void __launch_bounds__(256) split_kernel(
    const float* __restrict__ s, __half* __restrict__ h, __half* __restrict__ l, int n)
{
    int i = (blockIdx.x * blockDim.x + threadIdx.x) * 4;
    if (i >= n) return;
    float4 v = *(const float4*)(s + i);
    uint32_t H0, L0, H1, L1;
    splitpack(v.x, v.y, H0, L0);
    splitpack(v.z, v.w, H1, L1);
    *(uint32_t*)(h + i) = H0; *(uint32_t*)(h + i + 2) = H1;
    *(uint32_t*)(l + i) = L0; *(uint32_t*)(l + i + 2) = L1;
}

// ================= 3xFP16 GEMM on pre-split halves =================
// C = A @ B + bias.  EPI: 0 -> fp32 C; 1 -> half CH/CL + gelu; 2 -> half CH/CL.
template<int EPI>
__global__ void __launch_bounds__(256) gemm_h(
    const __half* __restrict__ AH, const __half* __restrict__ AL,
    const __half* __restrict__ BH, const __half* __restrict__ BL,
    const float* __restrict__ bias,
    float* __restrict__ Cf, __half* __restrict__ CH, __half* __restrict__ CL,
    int M, int N, int K)
{
    __shared__ __half AsH[128][40], AsL[128][40];
    __shared__ __half BsH[32][136], BsL[32][136];

    const int tid = threadIdx.x, warp = tid >> 5, lane = tid & 31;
    const int m0 = blockIdx.y * 128, n0 = blockIdx.x * 128;
    const int wm = (warp >> 2) * 64, wn = (warp & 3) * 32;
    const int g = lane >> 2, tg = lane & 3;

    const int am = tid >> 1, ac = (tid & 1) * 16;
    const int bk = tid >> 3, bn = (tid & 7) * 16;
    const __half* AHp = AH + (size_t)(m0 + am) * K + ac;
    const __half* ALp = AL + (size_t)(m0 + am) * K + ac;
    const __half* BHp = BH + n0 + bn;
    const __half* BLp = BL + n0 + bn;

    uint32_t asHb = s2u(&AsH[0][0]), asLb = s2u(&AsL[0][0]);
    uint32_t bsHb = s2u(&BsH[0][0]), bsLb = s2u(&BsL[0][0]);
    uint32_t aoff = (uint32_t)((wm + (lane & 15)) * 80 + (lane >> 4) * 16);
    uint32_t boff = (uint32_t)(((lane & 7) + 8 * ((lane >> 3) & 1)) * 272 + wn * 2);

    uint4 rah[2], ral[2], rbh[2], rbl[2];
    rah[0] = *(const uint4*)(AHp);     rah[1] = *(const uint4*)(AHp + 8);
    ral[0] = *(const uint4*)(ALp);     ral[1] = *(const uint4*)(ALp + 8);
    rbh[0] = *(const uint4*)(BHp + (size_t)bk * N);
    rbh[1] = *(const uint4*)(BHp + (size_t)bk * N + 8);
    rbl[0] = *(const uint4*)(BLp + (size_t)bk * N);
    rbl[1] = *(const uint4*)(BLp + (size_t)bk * N + 8);

    float acc[16][4];
    #pragma unroll
    for (int i = 0; i < 16; i++) { acc[i][0] = acc[i][1] = acc[i][2] = acc[i][3] = 0.f; }

    const int Tn = K >> 5;
    for (int t = 0; t < Tn; t++) {
        *(uint4*)&AsH[am][ac] = rah[0]; *(uint4*)&AsH[am][ac + 8] = rah[1];
        *(uint4*)&AsL[am][ac] = ral[0]; *(uint4*)&AsL[am][ac + 8] = ral[1];
        *(uint4*)&BsH[bk][bn] = rbh[0]; *(uint4*)&BsH[bk][bn + 8] = rbh[1];
        *(uint4*)&BsL[bk][bn] = rbl[0]; *(uint4*)&BsL[bk][bn + 8] = rbl[1];
        __syncthreads();
        if (t + 1 < Tn) {
            int k0 = (t + 1) << 5;
            rah[0] = *(const uint4*)(AHp + k0);     rah[1] = *(const uint4*)(AHp + k0 + 8);
            ral[0] = *(const uint4*)(ALp + k0);     ral[1] = *(const uint4*)(ALp + k0 + 8);
            rbh[0] = *(const uint4*)(BHp + (size_t)(k0 + bk) * N);
            rbh[1] = *(const uint4*)(BHp + (size_t)(k0 + bk) * N + 8);
            rbl[0] = *(const uint4*)(BLp + (size_t)(k0 + bk) * N);
            rbl[1] = *(const uint4*)(BLp + (size_t)(k0 + bk) * N + 8);
        }
        #pragma unroll
        for (int kk = 0; kk < 2; kk++) {
            uint32_t aH[4][4], aL[4][4], bH[4][2], bL[4][2];
            #pragma unroll
            for (int mf = 0; mf < 4; mf++) {
                ldmx4(aH[mf], asHb + aoff + mf * 1280 + kk * 32);
                ldmx4(aL[mf], asLb + aoff + mf * 1280 + kk * 32);
            }
            #pragma unroll
            for (int nf = 0; nf < 4; nf++) {
                ldmx2t(bH[nf], bsHb + boff + nf * 16 + kk * 4352);
                ldmx2t(bL[nf], bsLb + boff + nf * 16 + kk * 4352);
            }
            #pragma unroll
            for (int mf = 0; mf < 4; mf++)
                #pragma unroll
                for (int nf = 0; nf < 4; nf++) {
                    float* c = acc[mf * 4 + nf];
                    mma16816(c, aL[mf], bH[nf]);
                    mma16816(c, aH[mf], bL[nf]);
                    mma16816(c, aH[mf], bH[nf]);
                }
        }
        __syncthreads();
    }

    #pragma unroll
    for (int mf = 0; mf < 4; mf++)
        #pragma unroll
        for (int nf = 0; nf < 4; nf++) {
            const float* c = acc[mf * 4 + nf];
            int mrow = m0 + wm + mf * 16 + g;
            int ncol = n0 + wn + nf * 8 + tg * 2;
            float b0 = bias[ncol], b1 = bias[ncol + 1];
            float v0 = c[0] + b0, v1 = c[1] + b1, v2 = c[2] + b0, v3 = c[3] + b1;
            if (EPI == 1) { v0 = gelu_tanh(v0); v1 = gelu_tanh(v1); v2 = gelu_tanh(v2); v3 = gelu_tanh(v3); }
            if (EPI == 0) {
                Cf[(size_t)mrow * N + ncol]           = v0;
                Cf[(size_t)mrow * N + ncol + 1]       = v1;
                Cf[(size_t)(mrow + 8) * N + ncol]     = v2;
                Cf[(size_t)(mrow + 8) * N + ncol + 1] = v3;
            } else {
                uint32_t H, L;
                splitpack(v0, v1, H, L);
                *(uint32_t*)&CH[(size_t)mrow * N + ncol] = H;
                *(uint32_t*)&CL[(size_t)mrow * N + ncol] = L;
                splitpack(v2, v3, H, L);
                *(uint32_t*)&CH[(size_t)(mrow + 8) * N + ncol] = H;
                *(uint32_t*)&CL[(size_t)(mrow + 8) * N + ncol] = L;
            }
        }
}

// ================= fused flash attention (3xFP16 mma, online softmax) =================
// grid: (4 m-tiles, NBH). 256 threads, 8 warps x 16 query rows.
// Key tiles of 64, 8 iterations over the 512 keys.
#define ATTN_SMEM (73984)
__global__ void __launch_bounds__(256, 1) attn_fused(
    const __half* __restrict__ QKVH, const __half* __restrict__ QKVL,
    const int* __restrict__ amask,
    __half* __restrict__ CTXH, __half* __restrict__ CTXL)
{
    extern __shared__ char smraw[];
    __half* QsH = (__half*)smraw;          // [128][72]
    __half* QsL = QsH + 128 * 72;
    __half* KsH = QsL + 128 * 72;          // [64][72]
    __half* KsL = KsH + 64 * 72;
    __half* VsH = KsL + 64 * 72;           // [64][72]
    __half* VsL = VsH + 64 * 72;
    float*  mkf = (float*)(VsL + 64 * 72); // [64]

    const int tid = threadIdx.x, warp = tid >> 5, lane = tid & 31;
    const int bh = blockIdx.y, b = bh / NHH, h = bh % NHH;
    const int m0 = blockIdx.x * 128;
    const int g = lane >> 2, tg = lane & 3;

    // stage Q tile (pre-split halves straight from qkv)
    {
        int am = tid >> 1, ac = (tid & 1) * 32;
        const __half* qh = QKVH + (size_t)(b * NT + m0 + am) * T3 + h * DH + ac;
        const __half* ql = QKVL + (size_t)(b * NT + m0 + am) * T3 + h * DH + ac;
        #pragma unroll
        for (int i = 0; i < 4; i++) {
            *(uint4*)&QsH[am * 72 + ac + i * 8] = *(const uint4*)(qh + i * 8);
            *(uint4*)&QsL[am * 72 + ac + i * 8] = *(const uint4*)(ql + i * 8);
        }
    }
    __syncthreads();

    uint32_t qsHb = s2u(QsH), qsLb = s2u(QsL);
    uint32_t ksHb = s2u(KsH), ksLb = s2u(KsL);
    uint32_t vsHb = s2u(VsH), vsLb = s2u(VsL);
    uint32_t qoff = (uint32_t)((warp * 16 + (lane & 15)) * 144 + (lane >> 4) * 16);
    uint32_t koff = (uint32_t)((lane & 7) * 144 + ((lane >> 3) & 1) * 16);
    uint32_t voff = (uint32_t)(((lane & 7) + 8 * ((lane >> 3) & 1)) * 144);

    uint32_t qH[4][4], qL[4][4];
    #pragma unroll
    for (int kc = 0; kc < 4; kc++) {
        ldmx4(qH[kc], qsHb + qoff + kc * 32);
        ldmx4(qL[kc], qsLb + qoff + kc * 32);
    }

    float o[8][4];
    #pragma unroll
    for (int i = 0; i < 8; i++) { o[i][0] = o[i][1] = o[i][2] = o[i][3] = 0.f; }
    float mA = -1e30f, mB = -1e30f, lA = 0.f, lB = 0.f;

    const int krow = tid >> 2, kseg = (tid & 3) * 16;
    for (int kt = 0; kt < 8; kt++) {
        __syncthreads();   // previous tile fully consumed
        {
            int key = kt * 64 + krow;
            const __half* kh = QKVH + (size_t)(b * NT + key) * T3 + HD + h * DH + kseg;
            const __half* kl = QKVL + (size_t)(b * NT + key) * T3 + HD + h * DH + kseg;
            const __half* vh = QKVH + (size_t)(b * NT + key) * T3 + 2 * HD + h * DH + kseg;
            const __half* vl = QKVL + (size_t)(b * NT + key) * T3 + 2 * HD + h * DH + kseg;
            *(uint4*)&KsH[krow * 72 + kseg]     = *(const uint4*)(kh);
            *(uint4*)&KsH[krow * 72 + kseg + 8] = *(const uint4*)(kh + 8);
            *(uint4*)&KsL[krow * 72 + kseg]     = *(const uint4*)(kl);
            *(uint4*)&KsL[krow * 72 + kseg + 8] = *(const uint4*)(kl + 8);
            *(uint4*)&VsH[krow * 72 + kseg]     = *(const uint4*)(vh);
            *(uint4*)&VsH[krow * 72 + kseg + 8] = *(const uint4*)(vh + 8);
            *(uint4*)&VsL[krow * 72 + kseg]     = *(const uint4*)(vl);
            *(uint4*)&VsL[krow * 72 + kseg + 8] = *(const uint4*)(vl + 8);
            if (tid < 64) mkf[tid] = (1.f - (float)amask[b * NT + kt * 64 + tid]) * -1e9f;
        }
        __syncthreads();

        // S = Q @ K^T for this 16x64 warp tile
        float s[8][4];
        #pragma unroll
        for (int i = 0; i < 8; i++) { s[i][0] = s[i][1] = s[i][2] = s[i][3] = 0.f; }
        #pragma unroll
        for (int nf = 0; nf < 8; nf++) {
            #pragma unroll
            for (int kc = 0; kc < 4; kc++) {
                uint32_t bH[2], bL[2];
                ldmx2(bH, ksHb + koff + nf * 1152 + kc * 32);
                ldmx2(bL, ksLb + koff + nf * 1152 + kc * 32);
                mma16816(s[nf], qL[kc], bH);
                mma16816(s[nf], qH[kc], bL);
                mma16816(s[nf], qH[kc], bH);
            }
        }

        // scale + mask, row max
        float rmA = -1e30f, rmB = -1e30f;
        #pragma unroll
        for (int nf = 0; nf < 8; nf++) {
            float d0 = mkf[nf * 8 + tg * 2], d1 = mkf[nf * 8 + tg * 2 + 1];
            s[nf][0] = s[nf][0] * 0.125f + d0;
            s[nf][1] = s[nf][1] * 0.125f + d1;
            s[nf][2] = s[nf][2] * 0.125f + d0;
            s[nf][3] = s[nf][3] * 0.125f + d1;
            rmA = fmaxf(rmA, fmaxf(s[nf][0], s[nf][1]));
            rmB = fmaxf(rmB, fmaxf(s[nf][2], s[nf][3]));
        }
        rmA = fmaxf(rmA, __shfl_xor_sync(0xffffffffu, rmA, 1));
        rmA = fmaxf(rmA, __shfl_xor_sync(0xffffffffu, rmA, 2));
        rmB = fmaxf(rmB, __shfl_xor_sync(0xffffffffu, rmB, 1));
        rmB = fmaxf(rmB, __shfl_xor_sync(0xffffffffu, rmB, 2));

        float nmA = fmaxf(mA, rmA), nmB = fmaxf(mB, rmB);
        float cA = __expf(mA - nmA), cB = __expf(mB - nmB);
        float rsA = 0.f, rsB = 0.f;
        #pragma unroll
        for (int nf = 0; nf < 8; nf++) {
            s[nf][0] = __expf(s[nf][0] - nmA);
            s[nf][1] = __expf(s[nf][1] - nmA);
            s[nf][2] = __expf(s[nf][2] - nmB);
            s[nf][3] = __expf(s[nf][3] - nmB);
            rsA += s[nf][0] + s[nf][1];
            rsB += s[nf][2] + s[nf][3];
        }
        rsA += __shfl_xor_sync(0xffffffffu, rsA, 1);
        rsA += __shfl_xor_sync(0xffffffffu, rsA, 2);
        rsB += __shfl_xor_sync(0xffffffffu, rsB, 1);
        rsB += __shfl_xor_sync(0xffffffffu, rsB, 2);
        lA = lA * cA + rsA;
        lB = lB * cB + rsB;
        mA = nmA; mB = nmB;
        #pragma unroll
        for (int i = 0; i < 8; i++) {
            o[i][0] *= cA; o[i][1] *= cA;
            o[i][2] *= cB; o[i][3] *= cB;
        }

        // O += P @ V   (P from S fragments directly, split hi/lo)
        #pragma unroll
        for (int kc = 0; kc < 4; kc++) {
            uint32_t pH[4], pL[4];
            splitpack(s[2 * kc][0],     s[2 * kc][1],     pH[0], pL[0]);
            splitpack(s[2 * kc][2],     s[2 * kc][3],     pH[1], pL[1]);
            splitpack(s[2 * kc + 1][0], s[2 * kc + 1][1], pH[2], pL[2]);
            splitpack(s[2 * kc + 1][2], s[2 * kc + 1][3], pH[3], pL[3]);
            #pragma unroll
            for (int nf = 0; nf < 8; nf++) {
                uint32_t vH[2], vL[2];
                ldmx2t(vH, vsHb + voff + nf * 16 + kc * 2304);
                ldmx2t(vL, vsLb + voff + nf * 16 + kc * 2304);
                mma16816(o[nf], pL, vH);
                mma16816(o[nf], pH, vL);
                mma16816(o[nf], pH, vH);
            }
        }
    }

    // epilogue: O / l, split to halves
    float iA = 1.f / lA, iB = 1.f / lB;
    int rowA = b * NT + m0 + warp * 16 + g;
    #pragma unroll
    for (int nf = 0; nf < 8; nf++) {
        int ncol = h * DH + nf * 8 + tg * 2;
        uint32_t H, L;
        splitpack(o[nf][0] * iA, o[nf][1] * iA, H, L);
        *(uint32_t*)&CTXH[(size_t)rowA * HD + ncol] = H;
        *(uint32_t*)&CTXL[(size_t)rowA * HD + ncol] = L;
        splitpack(o[nf][2] * iB, o[nf][3] * iB, H, L);
        *(uint32_t*)&CTXH[(size_t)(rowA + 8) * HD + ncol] = H;
        *(uint32_t*)&CTXL[(size_t)(rowA + 8) * HD + ncol] = L;
    }
}

// ---------------- reductions ----------------
__device__ __forceinline__ void reduce2_256(float& a, float& b) {
    __shared__ float sa[8], sb[8];
    #pragma unroll
    for (int o = 16; o; o >>= 1) {
        a += __shfl_xor_sync(0xffffffffu, a, o);
        b += __shfl_xor_sync(0xffffffffu, b, o);
    }
    int w = threadIdx.x >> 5;
    if ((threadIdx.x & 31) == 0) { sa[w] = a; sb[w] = b; }
    __syncthreads();
    a = 0.f; b = 0.f;
    #pragma unroll
    for (int i = 0; i < 8; i++) { a += sa[i]; b += sb[i]; }
}

// ---------------- embedding + LN ----------------
__global__ void __launch_bounds__(256) embed_ln_kernel(
    const int* __restrict__ ids, const int* __restrict__ tt,
    const float* __restrict__ we, const float* __restrict__ pe, const float* __restrict__ te,
    const float* __restrict__ sc, const float* __restrict__ bi,
    float* __restrict__ x, __half* __restrict__ xh, __half* __restrict__ xl)
{
    int tok = blockIdx.x;
    int t   = tok & (NT - 1);
    int tid = threadIdx.x;
    const float* w  = we + (size_t)ids[tok] * HD;
    const float* p  = pe + (size_t)t * HD;
    const float* ty = te + (size_t)tt[tok] * HD;
    float e[3]; float sum = 0.f, sq = 0.f;
    #pragma unroll
    for (int i = 0; i < 3; i++) {
        int c = tid + i * 256;
        float v = w[c] + p[c] + ty[c];
        e[i] = v; sum += v; sq += v * v;
    }
    reduce2_256(sum, sq);
    float mean = sum * (1.f / HD);
    float var  = sq * (1.f / HD) - mean * mean;
    float inv  = rsqrtf(var + 1e-12f);
    #pragma unroll
    for (int i = 0; i < 3; i++) {
        int c = tid + i * 256;
        float v = (e[i] - mean) * inv * sc[c] + bi[c];
        size_t idx = (size_t)tok * HD + c;
        x[idx] = v;
        __half h = __float2half_rn(v);
        xh[idx] = h;
        xl[idx] = __float2half_rn(v - __half2float(h));
    }
}

// ---------------- residual + LN ----------------
__global__ void __launch_bounds__(256) ln_res_kernel(
    const float* __restrict__ xin, const float* __restrict__ y,
    const float* __restrict__ sc, const float* __restrict__ bi,
    float* __restrict__ xout, __half* __restrict__ xh, __half* __restrict__ xl)
{
    int tok = blockIdx.x;
    int tid = threadIdx.x;
    float e[3]; float sum = 0.f, sq = 0.f;
    #pragma unroll
    for (int i = 0; i < 3; i++) {
        int c = tid + i * 256;
        float v = xin[(size_t)tok * HD + c] + y[(size_t)tok * HD + c];
        e[i] = v; sum += v; sq += v * v;
    }
    reduce2_256(sum, sq);
    float mean = sum * (1.f / HD);
    float var  = sq * (1.f / HD) - mean * mean;
    float inv  = rsqrtf(var + 1e-12f);
    #pragma unroll
    for (int i = 0; i < 3; i++) {
        int c = tid + i * 256;
        float v = (e[i] - mean) * inv * sc[c] + bi[c];
        size_t idx = (size_t)tok * HD + c;
        xout[idx] = v;
        __half h = __float2half_rn(v);
        xh[idx] = h;
        xl[idx] = __float2half_rn(v - __half2float(h));
    }
}

// ---------------- classifier ----------------
__global__ void __launch_bounds__(256) cls_kernel(
    const float* __restrict__ x, const float* __restrict__ W,
    const float* __restrict__ bias, float* __restrict__ out)
{
    int idx = blockIdx.x * blockDim.x + threadIdx.x;
    if (idx >= TOK * NLB) return;
    int tok = idx / NLB, n = idx % NLB;
    const float* xr = x + (size_t)tok * HD;
    float s = bias[n];
    #pragma unroll 8
    for (int k = 0; k < HD; k++) s = fmaf(xr[k], W[k * NLB + n], s);
    out[idx] = s;
}

// ---------------- CRF ----------------
__global__ void __launch_bounds__(128) crf_kernel(
    const float* __restrict__ logits, const int* __restrict__ labels,
    const int* __restrict__ amask, const float* __restrict__ startv,
    const float* __restrict__ endv, const float* __restrict__ trans,
    float* __restrict__ llh, float* __restrict__ dout)
{
    __shared__ float em[511 * NLB];
    __shared__ float tr[NLB * NLB];
    __shared__ unsigned char bp[510 * NLB];
    __shared__ float mk[511];
    __shared__ int   tg[511];
    __shared__ float sd[NLB], sv[NLB];

    int b = blockIdx.x, tid = threadIdx.x;
    const float* lp = logits + (size_t)(b * NT + 1) * NLB;
    for (int i = tid; i < 511 * NLB; i += blockDim.x) em[i] = lp[i];
    for (int i = tid; i < NLB * NLB; i += blockDim.x) tr[i] = trans[i];
    for (int i = tid; i < 511; i += blockDim.x) {
        mk[i] = (float)amask[b * NT + 1 + i];
        tg[i] = labels[b * NT + 1 + i];
    }
    __syncthreads();

    if (tid < 32) {
        int j = tid;
        float tc[NLB];
        if (j < NLB) {
            #pragma unroll
            for (int i = 0; i < NLB; i++) tc[i] = tr[i * NLB + j];
            sd[j] = startv[j] + em[j];
            sv[j] = sd[j];
        }
        __syncwarp();
        float num = 0.f; int prev = 0;
        if (j == 0) { prev = tg[0]; num = startv[prev] + em[prev]; }

        for (int s = 1; s < 511; s++) {
            float m = mk[s];
            float nd = 0.f, nv = 0.f; int bi = 0;
            if (j < NLB) {
                float e = em[s * NLB + j];
                float mx = -1e30f;
                #pragma unroll
                for (int i = 0; i < NLB; i++) { float v = sd[i] + tc[i]; mx = fmaxf(mx, v); }
                float sum = 0.f;
                #pragma unroll
                for (int i = 0; i < NLB; i++) sum += __expf(sd[i] + tc[i] - mx);
                nd = mx + __logf(sum) + e;
                float bv = -1e30f;
                #pragma unroll
                for (int i = 0; i < NLB; i++) {
                    float v = sv[i] + tc[i];
                    if (v > bv) { bv = v; bi = i; }
                }
                bp[(s - 1) * NLB + j] = (unsigned char)bi;
                nv = bv + e;
            }
            __syncwarp();
            if (j < NLB && m > 0.f) { sd[j] = nd; sv[j] = nv; }
            if (j == 0) {
                int t = tg[s];
                num += m * (tr[prev * NLB + t] + em[s * NLB + t]);
                if (m > 0.f) prev = t;
            }
            __syncwarp();
        }

        if (j == 0) {
            num += endv[prev];
            float mx = -1e30f;
            #pragma unroll
            for (int i = 0; i < NLB; i++) mx = fmaxf(mx, sd[i] + endv[i]);
            float sum = 0.f;
            #pragma unroll
            for (int i = 0; i < NLB; i++) sum += __expf(sd[i] + endv[i] - mx);
            float den = mx + __logf(sum);
            llh[b] = num - den;

            float bv = -1e30f; int last = 0;
            #pragma unroll
            for (int i = 0; i < NLB; i++) {
                float v = sv[i] + endv[i];
                if (v > bv) { bv = v; last = i; }
            }
            float* pd = dout + 1 + (size_t)b * 511;
            pd[510] = (float)last;
            for (int s = 509; s >= 0; s--) {
                last = bp[s * NLB + last];
                pd[s] = (float)last;
            }
        }
    }
}

__global__ void loss_kernel(const float* __restrict__ llh, float* __restrict__ dout)
{
    if (threadIdx.x == 0) {
        float s = 0.f;
        for (int i = 0; i < NB; i++) s += llh[i];
        dout[0] = -s / (float)NB;
    }
}

// ---------------- launcher ----------------
extern "C" void kernel_launch(void* const* d_in, const int* in_sizes, int n_in,
                              void* d_out, int out_size)
{
    (void)in_sizes; (void)n_in; (void)out_size;
    const int*   ids  = (const int*)d_in[0];
    const int*   am   = (const int*)d_in[1];
    const int*   tti  = (const int*)d_in[2];
    const int*   lab  = (const int*)d_in[3];
    const float* we   = (const float*)d_in[4];
    const float* pe   = (const float*)d_in[5];
    const float* te   = (const float*)d_in[6];
    const float* elns = (const float*)d_in[7];
    const float* elnb = (const float*)d_in[8];
    const float* Wqkv = (const float*)d_in[9];
    const float* bqkv = (const float*)d_in[10];
    const float* Wo   = (const float*)d_in[11];
    const float* bo   = (const float*)d_in[12];
    const float* l1s  = (const float*)d_in[13];
    const float* l1b  = (const float*)d_in[14];
    const float* W1   = (const float*)d_in[15];
    const float* b1   = (const float*)d_in[16];
    const float* W2   = (const float*)d_in[17];
    const float* b2   = (const float*)d_in[18];
    const float* l2s  = (const float*)d_in[19];
    const float* l2b  = (const float*)d_in[20];
    const float* Wcls = (const float*)d_in[21];
    const float* bcls = (const float*)d_in[22];
    const float* cst  = (const float*)d_in[23];
    const float* cen  = (const float*)d_in[24];
    const float* ctr  = (const float*)d_in[25];
    float* out = (float*)d_out;

    float *x, *y, *lg, *llh;
    __half *xh, *xl, *qkvh, *qkvl, *ctxh, *ctxl, *ffh, *ffl;
    __half *wqh, *wql, *woh, *wol, *w1h, *w1l, *w2h, *w2l;
    cudaGetSymbolAddress((void**)&x,   g_x);
    cudaGetSymbolAddress((void**)&y,   g_y);
    cudaGetSymbolAddress((void**)&lg,  g_logits);
    cudaGetSymbolAddress((void**)&llh, g_llh);
    cudaGetSymbolAddress((void**)&xh,   g_xh);   cudaGetSymbolAddress((void**)&xl,   g_xl);
    cudaGetSymbolAddress((void**)&qkvh, g_qkvh); cudaGetSymbolAddress((void**)&qkvl, g_qkvl);
    cudaGetSymbolAddress((void**)&ctxh, g_ctxh); cudaGetSymbolAddress((void**)&ctxl, g_ctxl);
    cudaGetSymbolAddress((void**)&ffh,  g_ffh);  cudaGetSymbolAddress((void**)&ffl,  g_ffl);
    cudaGetSymbolAddress((void**)&wqh,  g_wqh);  cudaGetSymbolAddress((void**)&wql,  g_wql);
    cudaGetSymbolAddress((void**)&woh,  g_woh);  cudaGetSymbolAddress((void**)&wol,  g_wol);
    cudaGetSymbolAddress((void**)&w1h,  g_w1h);  cudaGetSymbolAddress((void**)&w1l,  g_w1l);
    cudaGetSymbolAddress((void**)&w2h,  g_w2h);  cudaGetSymbolAddress((void**)&w2l,  g_w2l);

    cudaFuncSetAttribute(attn_fused, cudaFuncAttributeMaxDynamicSharedMemorySize, ATTN_SMEM);

    // weight splits (once per launch)
    {
        int n;
        n = NLAY * HD * T3;  split_kernel<<<(n / 4 + 255) / 256, 256>>>(Wqkv, wqh, wql, n);
        n = NLAY * HD * HD;  split_kernel<<<(n / 4 + 255) / 256, 256>>>(Wo,   woh, wol, n);
        n = NLAY * HD * DFF; split_kernel<<<(n / 4 + 255) / 256, 256>>>(W1,   w1h, w1l, n);
        n = NLAY * DFF * HD; split_kernel<<<(n / 4 + 255) / 256, 256>>>(W2,   w2h, w2l, n);
    }

    embed_ln_kernel<<<TOK, 256>>>(ids, tti, we, pe, te, elns, elnb, x, xh, xl);

    for (int l = 0; l < NLAY; l++) {
        gemm_h<2><<<dim3(T3 / 128, TOK / 128), 256>>>(
            xh, xl, wqh + (size_t)l * HD * T3, wql + (size_t)l * HD * T3,
            bqkv + (size_t)l * T3, nullptr, qkvh, qkvl, TOK, T3, HD);
        attn_fused<<<dim3(4, NBH), 256, ATTN_SMEM>>>(qkvh, qkvl, am, ctxh, ctxl);
        gemm_h<0><<<dim3(HD / 128, TOK / 128), 256>>>(
            ctxh, ctxl, woh + (size_t)l * HD * HD, wol + (size_t)l * HD * HD,
            bo + (size_t)l * HD, y, nullptr, nullptr, TOK, HD, HD);
        ln_res_kernel<<<TOK, 256>>>(x, y, l1s + (size_t)l * HD, l1b + (size_t)l * HD, x, xh, xl);
        gemm_h<1><<<dim3(DFF / 128, TOK / 128), 256>>>(
            xh, xl, w1h + (size_t)l * HD * DFF, w1l + (size_t)l * HD * DFF,
            b1 + (size_t)l * DFF, nullptr, ffh, ffl, TOK, DFF, HD);
        gemm_h<0><<<dim3(HD / 128, TOK / 128), 256>>>(
            ffh, ffl, w2h + (size_t)l * DFF * HD, w2l + (size_t)l * DFF * HD,
            b2 + (size_t)l * HD, y, nullptr, nullptr, TOK, HD, DFF);
        ln_res_kernel<<<TOK, 256>>>(x, y, l2s + (size_t)l * HD, l2b + (size_t)l * HD, x, xh, xl);
    }

    cls_kernel<<<(TOK * NLB + 255) / 256, 256>>>(x, Wcls, bcls, lg);
    crf_kernel<<<NB, 128>>>(lg, lab, am, cst, cen, ctr, llh, out);
    loss_kernel<<<1, 32>>>(llh, out);
}